// round 13
// baseline (speedup 1.0000x reference)
#include <cuda_runtime.h>
#include <cuda_bf16.h>
#include <math.h>
#include <stdint.h>

// Problem dims
#define BN 128
#define LN 512
#define DN 256
#define AN 64
#define KS 512   // compact split storage: [hi | lo] x 256; 12-stage schedule via maps

// Output layout (concatenated, reference tuple order)
#define OFF_WQ  ((size_t)0)
#define OFF_WK  ((size_t)BN * LN * DN)
#define OFF_QW  ((size_t)2 * BN * LN * DN)
#define OFF_KW  (OFF_QW + (size_t)BN * LN)

// -------- scratch (device globals; no allocation allowed) --------
__device__ __nv_bfloat16 g_Q2 [(size_t)BN * LN * KS];    // [hi|lo] of Q
__device__ __nv_bfloat16 g_K2 [(size_t)BN * LN * KS];    // [hi|lo] of K
__device__ __nv_bfloat16 g_Qw2[(size_t)BN * LN * KS];    // [hi|lo] of Qw
__device__ __nv_bfloat16 g_W2t[(size_t)DN * KS];         // W_rel^T [hi|lo]
__device__ __nv_bfloat16 g_Wp2t[2 * 64 * KS];            // Wq^T / Wk^T [hi|lo]
// accumulators: proj writes base value; rel_fused REDs score-GEMM terms on top
__device__ float g_accQ[(size_t)BN * LN * AN];           // q_proj + rel@kp
__device__ float g_accK[(size_t)BN * LN * AN];           // k_proj + relT@qp
__device__ __nv_bfloat16 g_qph[(size_t)BN * LN * AN], g_qpl[(size_t)BN * LN * AN];
__device__ __nv_bfloat16 g_kph[(size_t)BN * LN * AN], g_kpl[(size_t)BN * LN * AN];
__device__ float g_logit_q[BN * LN];
__device__ float g_logit_k[BN * LN];

// ======================= helpers (baseline PTX only) =======================
__device__ __forceinline__ uint32_t smem_to_u32(const void* p) {
    uint32_t a;
    asm("{ .reg .u64 t; cvta.to.shared.u64 t, %1; cvt.u32.u64 %0, t; }" : "=r"(a) : "l"(p));
    return a;
}
#define SMEM_SWIZZLE_128B(o) ((o) ^ (((o) >> 3) & 0x70))

__device__ __forceinline__ void cp_async16(uint32_t saddr, const void* g) {
    asm volatile("cp.async.cg.shared.global [%0], [%1], 16;" :: "r"(saddr), "l"(g));
}
#define CP_COMMIT  asm volatile("cp.async.commit_group;" ::: "memory")
#define CP_WAIT(n) asm volatile("cp.async.wait_group %0;" :: "n"(n) : "memory")

__device__ __forceinline__ void ldmatrix_x4(uint32_t& r0, uint32_t& r1, uint32_t& r2,
                                            uint32_t& r3, uint32_t addr) {
    asm volatile("ldmatrix.sync.aligned.m8n8.x4.shared.b16 {%0,%1,%2,%3}, [%4];"
                 : "=r"(r0), "=r"(r1), "=r"(r2), "=r"(r3) : "r"(addr));
}
__device__ __forceinline__ void ldmatrix_x4_trans(uint32_t& r0, uint32_t& r1, uint32_t& r2,
                                                  uint32_t& r3, uint32_t addr) {
    asm volatile("ldmatrix.sync.aligned.m8n8.x4.trans.shared.b16 {%0,%1,%2,%3}, [%4];"
                 : "=r"(r0), "=r"(r1), "=r"(r2), "=r"(r3) : "r"(addr));
}
__device__ __forceinline__ void mma_bf16(float* c, uint32_t a0, uint32_t a1, uint32_t a2,
                                         uint32_t a3, uint32_t b0, uint32_t b1) {
    asm volatile(
        "mma.sync.aligned.m16n8k16.row.col.f32.bf16.bf16.f32 "
        "{%0,%1,%2,%3}, {%4,%5,%6,%7}, {%8,%9}, {%0,%1,%2,%3};"
        : "+f"(c[0]), "+f"(c[1]), "+f"(c[2]), "+f"(c[3])
        : "r"(a0), "r"(a1), "r"(a2), "r"(a3), "r"(b0), "r"(b1));
}
// vector fp32 reduction (sm_90+ baseline PTX feature)
__device__ __forceinline__ void red_add_v2(float* addr, float a, float b) {
    asm volatile("red.global.add.v2.f32 [%0], {%1, %2};"
                 :: "l"(addr), "f"(a), "f"(b) : "memory");
}

__device__ __forceinline__ void split2(float x, __nv_bfloat16& hi, __nv_bfloat16& lo) {
    hi = __float2bfloat16(x);
    lo = __float2bfloat16(x - __bfloat162float(hi));
}
union BF2 { __nv_bfloat16 h[2]; uint32_t u; };

// Stage maps: logical stage s (0..11) -> physical 64-col chunk in [hi|lo] storage.
// Pairing: s 0-3 hi*hi, 4-7 lo*hi, 8-11 hi*lo.
__device__ __forceinline__ int amap(int s) { return s < 8 ? s : s - 8; }
__device__ __forceinline__ int bmap(int s) { return s < 4 ? s : s - 4; }

// ======================= warp-MMA mainloop (128x128 tile) =======================
// 3-stage cp.async ring, ONE __syncthreads per stage.
#define NSTAGE  12
#define STAGE_BYTES 32768
#define SMEM_MMA (3 * STAGE_BYTES)

__device__ __forceinline__ void load_stage(uint32_t sbase,
    const __nv_bfloat16* __restrict__ A, const __nv_bfloat16* __restrict__ B,
    int s, int tid)
{
    const __nv_bfloat16* Ak = A + amap(s) * 64;
    const __nv_bfloat16* Bk = B + bmap(s) * 64;
#pragma unroll
    for (int i = 0; i < 4; ++i) {
        const int idx = tid + i * 256;            // 0..1023 16B chunks
        const int r = idx >> 3, c = idx & 7;
        const uint32_t off = SMEM_SWIZZLE_128B((uint32_t)(r * 128 + c * 16));
        cp_async16(sbase + off, Ak + (size_t)r * KS + c * 8);
        cp_async16(sbase + 16384 + off, Bk + (size_t)r * KS + c * 8);
    }
}

__device__ __forceinline__ void warp_mma_main(
    const __nv_bfloat16* __restrict__ A, const __nv_bfloat16* __restrict__ B,
    uint32_t smem_base, int tid, float acc[4][4][4])
{
    const int wid = tid >> 5, lane = tid & 31;
    const int mw = (wid >> 2) * 64, nw = (wid & 3) * 32;

    load_stage(smem_base + 0 * STAGE_BYTES, A, B, 0, tid); CP_COMMIT;
    load_stage(smem_base + 1 * STAGE_BYTES, A, B, 1, tid); CP_COMMIT;

    for (int s = 0; s < NSTAGE; ++s) {
        CP_WAIT(1);            // stage s group complete (groups retire in order)
        __syncthreads();       // publish stage s; fences reuse of buf[(s+2)%3]
        if (s + 2 < NSTAGE)
            load_stage(smem_base + ((s + 2) % 3) * STAGE_BYTES, A, B, s + 2, tid);
        CP_COMMIT;

        const uint32_t sA = smem_base + (s % 3) * STAGE_BYTES;
        const uint32_t sB = sA + 16384;
#pragma unroll
        for (int kk = 0; kk < 64; kk += 16) {
            uint32_t a[4][4], b[4][2];
#pragma unroll
            for (int mf = 0; mf < 4; ++mf) {
                const uint32_t off = SMEM_SWIZZLE_128B((uint32_t)(
                    (mw + mf * 16 + (lane & 15)) * 128 + kk * 2 + ((lane >> 4) << 4)));
                ldmatrix_x4(a[mf][0], a[mf][1], a[mf][2], a[mf][3], sA + off);
            }
#pragma unroll
            for (int nb = 0; nb < 2; ++nb) {
                const int row = nw + nb * 16 + ((lane >> 4) & 1) * 8 + (lane & 7);
                const int kof = kk * 2 + (((lane >> 3) & 1) << 4);
                const uint32_t off = SMEM_SWIZZLE_128B((uint32_t)(row * 128 + kof));
                ldmatrix_x4(b[nb * 2][0], b[nb * 2][1], b[nb * 2 + 1][0], b[nb * 2 + 1][1],
                            sB + off);
            }
#pragma unroll
            for (int mf = 0; mf < 4; ++mf)
#pragma unroll
                for (int nf = 0; nf < 4; ++nf)
                    mma_bf16(acc[mf][nf], a[mf][0], a[mf][1], a[mf][2], a[mf][3],
                             b[nf][0], b[nf][1]);
        }
    }
    __syncthreads();   // all warps done with ring before caller reuses smem
}

// ======================= fused rel + att-score kernel =======================
#define R_PITCH  272          // 128 cols bf16 (256B) + 16B pad
#define P_PITCH  144          // 64 cols bf16 (128B) + 16B pad
#define RH_OFF   0
#define RL_OFF   34816
#define PJH_OFF  69632
#define PJL_OFF  88064
#define SMEM_FUSED 106496     // >= 3*STAGE_BYTES mainloop ring

__global__ void __launch_bounds__(256, 2) rel_fused_kernel(
    const __nv_bfloat16* __restrict__ Qw2, const __nv_bfloat16* __restrict__ K2,
    const __nv_bfloat16* __restrict__ kph, const __nv_bfloat16* __restrict__ kpl,
    const __nv_bfloat16* __restrict__ qph, const __nv_bfloat16* __restrict__ qpl,
    float* __restrict__ accQ, float* __restrict__ accK)
{
    extern __shared__ char smem[];
    const uint32_t sb = smem_to_u32(smem);
    const int tid = threadIdx.x, wid = tid >> 5, lane = tid & 31;
    const int mt = blockIdx.x, nt = blockIdx.y, b = blockIdx.z;
    const int m0 = mt * 128, n0 = nt * 128;

    float acc[4][4][4] = {};
    warp_mma_main(Qw2 + ((size_t)b * LN + m0) * KS,
                  K2  + ((size_t)b * LN + n0) * KS, sb, tid, acc);

    // prefetch kp hi/lo tiles (rows n0..n0+127) while storing rel to smem
    {
        const __nv_bfloat16* kh = kph + ((size_t)b * LN + n0) * AN;
        const __nv_bfloat16* kl = kpl + ((size_t)b * LN + n0) * AN;
#pragma unroll
        for (int i = 0; i < 4; ++i) {
            const int idx = tid + i * 256, r = idx >> 3, c = idx & 7;
            cp_async16(sb + PJH_OFF + r * P_PITCH + c * 16, kh + (size_t)r * AN + c * 8);
            cp_async16(sb + PJL_OFF + r * P_PITCH + c * 16, kl + (size_t)r * AN + c * 8);
        }
        CP_COMMIT;
    }

    // tanh + hi/lo split -> smem rel tiles
    const int mw = (wid >> 2) * 64, nw = (wid & 3) * 32;
    const int lr = lane >> 2, lc = (lane & 3) * 2;
#pragma unroll
    for (int mf = 0; mf < 4; ++mf)
#pragma unroll
        for (int nf = 0; nf < 4; ++nf)
#pragma unroll
            for (int p = 0; p < 2; ++p) {
                const int rr = mw + mf * 16 + lr + p * 8;
                const int cc = nw + nf * 8 + lc;
                BF2 H, L;
                split2(tanhf(acc[mf][nf][2 * p + 0]), H.h[0], L.h[0]);
                split2(tanhf(acc[mf][nf][2 * p + 1]), H.h[1], L.h[1]);
                *(uint32_t*)(smem + RH_OFF + rr * R_PITCH + cc * 2) = H.u;
                *(uint32_t*)(smem + RL_OFF + rr * R_PITCH + cc * 2) = L.u;
            }
    CP_WAIT(0);
    __syncthreads();

    // ---- C2[m][a] = sum_n rel[m][n] * kp[n0+n][a]
    // 3-term split with frags loaded ONCE per kk: aH*bH + aL*bH + aH*bL
    float c2[8][4] = {};
#pragma unroll
    for (int kk = 0; kk < 128; kk += 16) {
        uint32_t aH0, aH1, aH2, aH3, aL0, aL1, aL2, aL3;
        const uint32_t aoff = (16 * wid + (lane & 15)) * R_PITCH
                            + (kk + ((lane >> 4) << 3)) * 2;
        ldmatrix_x4(aH0, aH1, aH2, aH3, sb + RH_OFF + aoff);
        ldmatrix_x4(aL0, aL1, aL2, aL3, sb + RL_OFF + aoff);
#pragma unroll
        for (int ab = 0; ab < 4; ++ab) {
            uint32_t h0, h1, h2, h3, l0, l1, l2, l3;
            const uint32_t boff = (kk + (lane & 15)) * P_PITCH
                                + (ab * 16 + ((lane >> 4) << 3)) * 2;
            ldmatrix_x4_trans(h0, h1, h2, h3, sb + PJH_OFF + boff);
            ldmatrix_x4_trans(l0, l1, l2, l3, sb + PJL_OFF + boff);
            mma_bf16(c2[2 * ab],     aH0, aH1, aH2, aH3, h0, h1);
            mma_bf16(c2[2 * ab],     aL0, aL1, aL2, aL3, h0, h1);
            mma_bf16(c2[2 * ab],     aH0, aH1, aH2, aH3, l0, l1);
            mma_bf16(c2[2 * ab + 1], aH0, aH1, aH2, aH3, h2, h3);
            mma_bf16(c2[2 * ab + 1], aL0, aL1, aL2, aL3, h2, h3);
            mma_bf16(c2[2 * ab + 1], aH0, aH1, aH2, aH3, l2, l3);
        }
    }
    {
        float* base = accQ + ((size_t)b * LN + m0 + 16 * wid) * AN;
#pragma unroll
        for (int j = 0; j < 8; ++j) {
            const int col = j * 8 + lc;
            red_add_v2(base + (size_t)lr * AN + col,       c2[j][0], c2[j][1]);
            red_add_v2(base + (size_t)(lr + 8) * AN + col, c2[j][2], c2[j][3]);
        }
    }
    __syncthreads();   // all warps done reading kp tiles

    // load qp hi/lo tiles (rows m0..m0+127) into same region
    {
        const __nv_bfloat16* qh = qph + ((size_t)b * LN + m0) * AN;
        const __nv_bfloat16* ql = qpl + ((size_t)b * LN + m0) * AN;
#pragma unroll
        for (int i = 0; i < 4; ++i) {
            const int idx = tid + i * 256, r = idx >> 3, c = idx & 7;
            cp_async16(sb + PJH_OFF + r * P_PITCH + c * 16, qh + (size_t)r * AN + c * 8);
            cp_async16(sb + PJL_OFF + r * P_PITCH + c * 16, ql + (size_t)r * AN + c * 8);
        }
        CP_COMMIT; CP_WAIT(0);
    }
    __syncthreads();

    // ---- C3[n][a] = sum_m rel[m][n] * qp[m0+m][a]  (A = rel^T via ldmatrix.trans)
    float c3[8][4] = {};
    const int g = lane >> 3;
#pragma unroll
    for (int kk = 0; kk < 128; kk += 16) {
        uint32_t aH0, aH1, aH2, aH3, aL0, aL1, aL2, aL3;
        const uint32_t aoff = (kk + ((g >> 1) << 3) + (lane & 7)) * R_PITCH
                            + (16 * wid + ((g & 1) << 3)) * 2;
        ldmatrix_x4_trans(aH0, aH1, aH2, aH3, sb + RH_OFF + aoff);
        ldmatrix_x4_trans(aL0, aL1, aL2, aL3, sb + RL_OFF + aoff);
#pragma unroll
        for (int ab = 0; ab < 4; ++ab) {
            uint32_t h0, h1, h2, h3, l0, l1, l2, l3;
            const uint32_t boff = (kk + (lane & 15)) * P_PITCH
                                + (ab * 16 + ((lane >> 4) << 3)) * 2;
            ldmatrix_x4_trans(h0, h1, h2, h3, sb + PJH_OFF + boff);
            ldmatrix_x4_trans(l0, l1, l2, l3, sb + PJL_OFF + boff);
            mma_bf16(c3[2 * ab],     aH0, aH1, aH2, aH3, h0, h1);
            mma_bf16(c3[2 * ab],     aL0, aL1, aL2, aL3, h0, h1);
            mma_bf16(c3[2 * ab],     aH0, aH1, aH2, aH3, l0, l1);
            mma_bf16(c3[2 * ab + 1], aH0, aH1, aH2, aH3, h2, h3);
            mma_bf16(c3[2 * ab + 1], aL0, aL1, aL2, aL3, h2, h3);
            mma_bf16(c3[2 * ab + 1], aH0, aH1, aH2, aH3, l2, l3);
        }
    }
    {
        float* base = accK + ((size_t)b * LN + n0 + 16 * wid) * AN;
#pragma unroll
        for (int j = 0; j < 8; ++j) {
            const int col = j * 8 + lc;
            red_add_v2(base + (size_t)lr * AN + col,       c3[j][0], c3[j][1]);
            red_add_v2(base + (size_t)(lr + 8) * AN + col, c3[j][2], c3[j][3]);
        }
    }
}

// ======================= fused qw + proj launch ==============================
// even blockIdx.x -> qw tile (n fastest for Q2 L2 reuse); odd -> proj tile.
// Interleaving co-resides one qw CTA + one proj CTA per SM: their cp.async
// stalls and HMMA/LDSM phases overlap, lifting issue utilization of both.
#define SLIM_STAGE 24576

__device__ __forceinline__ void load_stage_slim(uint32_t sbase,
    const __nv_bfloat16* __restrict__ A, const __nv_bfloat16* __restrict__ W,
    int s, int tid)
{
    const __nv_bfloat16* Ak = A + amap(s) * 64;
    const __nv_bfloat16* Wk = W + bmap(s) * 64;
#pragma unroll
    for (int i = 0; i < 4; ++i) {
        const int idx = tid + i * 256;            // 1024 chunks: A 128 rows x 8
        const int r = idx >> 3, c = idx & 7;
        const uint32_t off = SMEM_SWIZZLE_128B((uint32_t)(r * 128 + c * 16));
        cp_async16(sbase + off, Ak + (size_t)r * KS + c * 8);
    }
#pragma unroll
    for (int i = 0; i < 2; ++i) {
        const int idx = tid + i * 256;            // 512 chunks: W 64 rows x 8
        const int r = idx >> 3, c = idx & 7;
        const uint32_t off = SMEM_SWIZZLE_128B((uint32_t)(r * 128 + c * 16));
        cp_async16(sbase + 16384 + off, Wk + (size_t)r * KS + c * 8);
    }
}

__device__ void qw_body(uint32_t sb, int bx, int tid,
    const __nv_bfloat16* __restrict__ Q2, const __nv_bfloat16* __restrict__ W2t,
    __nv_bfloat16* __restrict__ Qw2)
{
    const int m0 = (bx >> 1) * 128, n0 = (bx & 1) * 128;   // n fastest
    float acc[4][4][4] = {};
    warp_mma_main(Q2 + (size_t)m0 * KS, W2t + (size_t)n0 * KS, sb, tid, acc);

    const int wid = tid >> 5, lane = tid & 31;
    const int mw = (wid >> 2) * 64, nw = (wid & 3) * 32;
    const int lr = lane >> 2, lc = (lane & 3) * 2;
#pragma unroll
    for (int mf = 0; mf < 4; ++mf) {
        const int row = m0 + mw + mf * 16 + lr;
#pragma unroll
        for (int nf = 0; nf < 4; ++nf) {
            const int col = n0 + nw + nf * 8 + lc;
#pragma unroll
            for (int p = 0; p < 2; ++p) {
                const int rr = row + p * 8;
                BF2 H, L;
                split2(acc[mf][nf][2 * p + 0], H.h[0], L.h[0]);
                split2(acc[mf][nf][2 * p + 1], H.h[1], L.h[1]);
                __nv_bfloat16* o = Qw2 + (size_t)rr * KS + col;
                *(uint32_t*)(o)       = H.u;
                *(uint32_t*)(o + 256) = L.u;
            }
        }
    }
}

__device__ void proj_body(uint32_t sb, int px, int tid,
    const __nv_bfloat16* __restrict__ Q2, const __nv_bfloat16* __restrict__ K2,
    const __nv_bfloat16* __restrict__ Wp2t,
    float* __restrict__ accQ, float* __restrict__ accK,
    __nv_bfloat16* __restrict__ qph, __nv_bfloat16* __restrict__ qpl,
    __nv_bfloat16* __restrict__ kph, __nv_bfloat16* __restrict__ kpl)
{
    const int wid = tid >> 5, lane = tid & 31;
    const int side = px & 1;
    const int m0 = (px >> 1) * 128;
    const __nv_bfloat16* A = (side ? K2 : Q2) + (size_t)m0 * KS;
    const __nv_bfloat16* W = Wp2t + (size_t)side * 64 * KS;
    float* pf = side ? accK : accQ;
    __nv_bfloat16* ph = side ? kph : qph;
    __nv_bfloat16* pl = side ? kpl : qpl;

    const int mw = (wid >> 1) * 32, nw = (wid & 1) * 32;

    float acc[2][4][4] = {};
    load_stage_slim(sb + 0 * SLIM_STAGE, A, W, 0, tid); CP_COMMIT;
    load_stage_slim(sb + 1 * SLIM_STAGE, A, W, 1, tid); CP_COMMIT;

    for (int s = 0; s < NSTAGE; ++s) {
        CP_WAIT(1);
        __syncthreads();
        if (s + 2 < NSTAGE)
            load_stage_slim(sb + ((s + 2) % 3) * SLIM_STAGE, A, W, s + 2, tid);
        CP_COMMIT;

        const uint32_t sA = sb + (s % 3) * SLIM_STAGE;
        const uint32_t sW = sA + 16384;
#pragma unroll
        for (int kk = 0; kk < 64; kk += 16) {
            uint32_t a[2][4], b[4][2];
#pragma unroll
            for (int mf = 0; mf < 2; ++mf) {
                const uint32_t off = SMEM_SWIZZLE_128B((uint32_t)(
                    (mw + mf * 16 + (lane & 15)) * 128 + kk * 2 + ((lane >> 4) << 4)));
                ldmatrix_x4(a[mf][0], a[mf][1], a[mf][2], a[mf][3], sA + off);
            }
#pragma unroll
            for (int nb = 0; nb < 2; ++nb) {
                const int row = nw + nb * 16 + ((lane >> 4) & 1) * 8 + (lane & 7);
                const int kof = kk * 2 + (((lane >> 3) & 1) << 4);
                const uint32_t off = SMEM_SWIZZLE_128B((uint32_t)(row * 128 + kof));
                ldmatrix_x4(b[nb * 2][0], b[nb * 2][1], b[nb * 2 + 1][0], b[nb * 2 + 1][1],
                            sW + off);
            }
#pragma unroll
            for (int mf = 0; mf < 2; ++mf)
#pragma unroll
                for (int nf = 0; nf < 4; ++nf)
                    mma_bf16(acc[mf][nf], a[mf][0], a[mf][1], a[mf][2], a[mf][3],
                             b[nf][0], b[nf][1]);
        }
    }

    const int lr = lane >> 2, lc = (lane & 3) * 2;
#pragma unroll
    for (int mf = 0; mf < 2; ++mf) {
#pragma unroll
        for (int nf = 0; nf < 4; ++nf) {
            const int col = nw + nf * 8 + lc;
#pragma unroll
            for (int p = 0; p < 2; ++p) {
                const int row = m0 + mw + mf * 16 + lr + p * 8;
                const float v0 = acc[mf][nf][2 * p + 0];
                const float v1 = acc[mf][nf][2 * p + 1];
                *(float2*)(pf + (size_t)row * AN + col) = make_float2(v0, v1);
                BF2 H, L;
                split2(v0, H.h[0], L.h[0]);
                split2(v1, H.h[1], L.h[1]);
                *(uint32_t*)(ph + (size_t)row * AN + col) = H.u;
                *(uint32_t*)(pl + (size_t)row * AN + col) = L.u;
            }
        }
    }
}

__global__ void __launch_bounds__(256, 2) fused_qp_kernel(
    const __nv_bfloat16* __restrict__ Q2, const __nv_bfloat16* __restrict__ K2,
    const __nv_bfloat16* __restrict__ W2t, const __nv_bfloat16* __restrict__ Wp2t,
    __nv_bfloat16* __restrict__ Qw2,
    float* __restrict__ accQ, float* __restrict__ accK,
    __nv_bfloat16* __restrict__ qph, __nv_bfloat16* __restrict__ qpl,
    __nv_bfloat16* __restrict__ kph, __nv_bfloat16* __restrict__ kpl)
{
    extern __shared__ char smem[];
    const uint32_t sb = smem_to_u32(smem);
    const int tid = threadIdx.x;
    const int bx = blockIdx.x;
    if ((bx & 1) == 0)
        qw_body(sb, bx >> 1, tid, Q2, W2t, Qw2);
    else
        proj_body(sb, bx >> 1, tid, Q2, K2, Wp2t, accQ, accK, qph, qpl, kph, kpl);
}

// ======================= split / prep kernels =======================
// 8 elems per thread, uint4 (16B) stores
__global__ void __launch_bounds__(256) split_kernel(
    const float* __restrict__ Q, const float* __restrict__ Kmat,
    __nv_bfloat16* __restrict__ Q2, __nv_bfloat16* __restrict__ K2)
{
    const int sel = blockIdx.y;
    const float* src = sel ? Kmat : Q;
    __nv_bfloat16* dst = sel ? K2 : Q2;
    const size_t i8 = (size_t)blockIdx.x * 256 + threadIdx.x;   // per 8 elems
    const size_t row = i8 >> 5;
    const int c = (int)(i8 & 31) * 8;
    const float4 v0 = ((const float4*)src)[i8 * 2];
    const float4 v1 = ((const float4*)src)[i8 * 2 + 1];
    union { __nv_bfloat16 b[8]; uint4 u; } h, l;
    split2(v0.x, h.b[0], l.b[0]); split2(v0.y, h.b[1], l.b[1]);
    split2(v0.z, h.b[2], l.b[2]); split2(v0.w, h.b[3], l.b[3]);
    split2(v1.x, h.b[4], l.b[4]); split2(v1.y, h.b[5], l.b[5]);
    split2(v1.z, h.b[6], l.b[6]); split2(v1.w, h.b[7], l.b[7]);
    __nv_bfloat16* o = dst + row * KS + c;
    *(uint4*)(o)       = h.u;
    *(uint4*)(o + 256) = l.u;
}

__global__ void __launch_bounds__(256) prep_w2t(
    const float* __restrict__ Wrel, __nv_bfloat16* __restrict__ W2t)
{
    const int idx = blockIdx.x * 256 + threadIdx.x;   // 65536
    const int d = idx >> 8, n = idx & 255;
    __nv_bfloat16 hi, lo;
    split2(Wrel[d * 256 + n], hi, lo);
    W2t[(size_t)n * KS + d]       = hi;
    W2t[(size_t)n * KS + 256 + d] = lo;
}

__global__ void __launch_bounds__(256) prep_wp(
    const float* __restrict__ Wq, const float* __restrict__ Wk,
    __nv_bfloat16* __restrict__ Wp2t)
{
    const int idx = blockIdx.x * 256 + threadIdx.x;   // 32768
    const int side = idx >> 14;
    const int d = (idx >> 6) & 255, a = idx & 63;
    const float* W = side ? Wk : Wq;
    __nv_bfloat16 hi, lo;
    split2(W[d * 64 + a], hi, lo);
    __nv_bfloat16* slab = Wp2t + (size_t)side * 64 * KS;
    slab[(size_t)a * KS + d]       = hi;
    slab[(size_t)a * KS + 256 + d] = lo;
}

// ======================= tanh + dot reduce (reads accumulators) =============
__global__ void __launch_bounds__(256) att_reduce_kernel(
    const float* __restrict__ accQ, const float* __restrict__ accK,
    const float* __restrict__ Wqa, const float* __restrict__ Wka,
    float* __restrict__ lq, float* __restrict__ lk)
{
    const int side = blockIdx.y;
    const int wid = threadIdx.x >> 5, lane = threadIdx.x & 31;
    const size_t gm = (size_t)blockIdx.x * 8 + wid;   // b*LN + m
    const float* acc = side ? accK : accQ;
    const float* w   = side ? Wka  : Wqa;
    float* out       = side ? lk   : lq;

    float s = 0.f;
#pragma unroll
    for (int h = 0; h < 2; ++h) {
        const int a = lane + h * 32;
        s += tanhf(acc[gm * AN + a]) * w[a];
    }
#pragma unroll
    for (int o = 16; o; o >>= 1) s += __shfl_xor_sync(0xFFFFFFFFu, s, o);
    if (lane == 0) out[gm] = s;
}

// ============================================================================
__global__ void __launch_bounds__(512) softmax_kernel(
    const float* __restrict__ lq, const float* __restrict__ lk,
    float* __restrict__ out)
{
    __shared__ float red[512];
    const int b = blockIdx.x, sel = blockIdx.y, t = threadIdx.x;
    const float* l = (sel ? lk : lq) + (size_t)b * LN;
    float* o = out + (sel ? OFF_KW : OFF_QW) + (size_t)b * LN;

    float v = l[t];
    red[t] = v; __syncthreads();
    for (int s = 256; s > 0; s >>= 1) {
        if (t < s) red[t] = fmaxf(red[t], red[t + s]);
        __syncthreads();
    }
    const float mx = red[0];
    __syncthreads();
    const float e = expf(v - mx);
    red[t] = e; __syncthreads();
    for (int s = 256; s > 0; s >>= 1) {
        if (t < s) red[t] += red[t + s];
        __syncthreads();
    }
    o[t] = e / red[0];
}

// weighted outputs from compact bf16 [hi|lo] (exact to ~1e-5): q = hi + lo
__global__ void __launch_bounds__(256) scale_kernel(
    const __nv_bfloat16* __restrict__ Q2, const __nv_bfloat16* __restrict__ K2,
    float* __restrict__ out)
{
    const int sel = blockIdx.y;
    const size_t i4 = (size_t)blockIdx.x * 256 + threadIdx.x;
    const __nv_bfloat16* src = sel ? K2 : Q2;
    const float* w = out + (sel ? OFF_KW : OFF_QW);
    float4* dst = (float4*)(out + (sel ? OFF_WK : OFF_WQ));

    const size_t e = i4 * 4;
    const size_t row = e >> 8;            // b*LN + l
    const int c = (int)(e & 255);
    const float s = w[row];

    const __nv_bfloat16* p = src + row * KS + c;
    union { __nv_bfloat16 b[4]; uint2 u; } h, l;
    h.u = *(const uint2*)(p);
    l.u = *(const uint2*)(p + 256);
    float4 v;
    v.x = (__bfloat162float(h.b[0]) + __bfloat162float(l.b[0])) * s;
    v.y = (__bfloat162float(h.b[1]) + __bfloat162float(l.b[1])) * s;
    v.z = (__bfloat162float(h.b[2]) + __bfloat162float(l.b[2])) * s;
    v.w = (__bfloat162float(h.b[3]) + __bfloat162float(l.b[3])) * s;
    dst[i4] = v;
}

// ============================================================================
extern "C" void kernel_launch(void* const* d_in, const int* in_sizes, int n_in,
                              void* d_out, int out_size)
{
    (void)in_sizes; (void)n_in; (void)out_size;
    const float* Q    = (const float*)d_in[0];
    const float* Km   = (const float*)d_in[1];
    const float* Wrel = (const float*)d_in[2];
    const float* Wq   = (const float*)d_in[3];
    const float* Wk   = (const float*)d_in[4];
    const float* Wqa  = (const float*)d_in[5];
    const float* Wka  = (const float*)d_in[6];
    float* out = (float*)d_out;

    __nv_bfloat16 *q2, *k2, *qw2, *w2t, *wp2t, *qph, *qpl, *kph, *kpl;
    float *aQ, *aK, *lq, *lk;
    cudaGetSymbolAddress((void**)&q2,   g_Q2);
    cudaGetSymbolAddress((void**)&k2,   g_K2);
    cudaGetSymbolAddress((void**)&qw2,  g_Qw2);
    cudaGetSymbolAddress((void**)&w2t,  g_W2t);
    cudaGetSymbolAddress((void**)&wp2t, g_Wp2t);
    cudaGetSymbolAddress((void**)&aQ,   g_accQ);
    cudaGetSymbolAddress((void**)&aK,   g_accK);
    cudaGetSymbolAddress((void**)&qph,  g_qph);
    cudaGetSymbolAddress((void**)&qpl,  g_qpl);
    cudaGetSymbolAddress((void**)&kph,  g_kph);
    cudaGetSymbolAddress((void**)&kpl,  g_kpl);
    cudaGetSymbolAddress((void**)&lq,   g_logit_q);
    cudaGetSymbolAddress((void**)&lk,   g_logit_k);

    cudaFuncSetAttribute(fused_qp_kernel,  cudaFuncAttributeMaxDynamicSharedMemorySize, SMEM_MMA);
    cudaFuncSetAttribute(rel_fused_kernel, cudaFuncAttributeMaxDynamicSharedMemorySize, SMEM_FUSED);

    const dim3 blk(256);
    // compact [hi|lo] splits of inputs + weight transposes
    split_kernel<<<dim3((BN * LN * DN) / 8 / 256, 2), blk>>>(Q, Km, q2, k2);
    prep_w2t<<<256, blk>>>(Wrel, w2t);
    prep_wp<<<128, blk>>>(Wq, Wk, wp2t);
    // qw + projections, interleaved in ONE launch (co-resident per SM)
    fused_qp_kernel<<<2048, blk, SMEM_MMA>>>(
        q2, k2, w2t, wp2t, qw2, aQ, aK, qph, qpl, kph, kpl);
    // fused rel + both score GEMMs -> vector REDs into accumulators
    rel_fused_kernel<<<dim3(4, 4, BN), blk, SMEM_FUSED>>>(qw2, k2, kph, kpl, qph, qpl, aQ, aK);
    // tanh + @W_att -> logits
    att_reduce_kernel<<<dim3(BN * LN / 8, 2), blk>>>(aQ, aK, Wqa, Wka, lq, lk);
    // softmax -> weights in d_out
    softmax_kernel<<<dim3(BN, 2), 512>>>(lq, lk, out);
    // weighted outputs from compact bf16
    scale_kernel<<<dim3((BN * LN * DN) / 4 / 256, 2), 256>>>(q2, k2, out);
}

// round 14
// speedup vs baseline: 1.0266x; 1.0266x over previous
#include <cuda_runtime.h>
#include <cuda_bf16.h>
#include <math.h>
#include <stdint.h>

// Problem dims
#define BN 128
#define LN 512
#define DN 256
#define AN 64
#define KS 512   // compact split storage: [hi | lo] x 256; 12-stage schedule via maps

// Output layout (concatenated, reference tuple order)
#define OFF_WQ  ((size_t)0)
#define OFF_WK  ((size_t)BN * LN * DN)
#define OFF_QW  ((size_t)2 * BN * LN * DN)
#define OFF_KW  (OFF_QW + (size_t)BN * LN)

// -------- scratch (device globals; no allocation allowed) --------
__device__ __nv_bfloat16 g_Q2 [(size_t)BN * LN * KS];    // [hi|lo] of Q
__device__ __nv_bfloat16 g_K2 [(size_t)BN * LN * KS];    // [hi|lo] of K
__device__ __nv_bfloat16 g_Qw2[(size_t)BN * LN * KS];    // [hi|lo] of Qw
__device__ __nv_bfloat16 g_W2t[(size_t)DN * KS];         // W_rel^T [hi|lo]
__device__ __nv_bfloat16 g_Wp2t[2 * 64 * KS];            // Wq^T / Wk^T [hi|lo]
// accumulators: proj writes base value; rel_fused REDs score-GEMM terms on top
__device__ float g_accQ[(size_t)BN * LN * AN];           // q_proj + rel@kp
__device__ float g_accK[(size_t)BN * LN * AN];           // k_proj + relT@qp
__device__ __nv_bfloat16 g_qph[(size_t)BN * LN * AN], g_qpl[(size_t)BN * LN * AN];
__device__ __nv_bfloat16 g_kph[(size_t)BN * LN * AN], g_kpl[(size_t)BN * LN * AN];
__device__ float g_logit_q[BN * LN];
__device__ float g_logit_k[BN * LN];

// ======================= helpers (baseline PTX only) =======================
__device__ __forceinline__ uint32_t smem_to_u32(const void* p) {
    uint32_t a;
    asm("{ .reg .u64 t; cvta.to.shared.u64 t, %1; cvt.u32.u64 %0, t; }" : "=r"(a) : "l"(p));
    return a;
}
#define SMEM_SWIZZLE_128B(o) ((o) ^ (((o) >> 3) & 0x70))

__device__ __forceinline__ void cp_async16(uint32_t saddr, const void* g) {
    asm volatile("cp.async.cg.shared.global [%0], [%1], 16;" :: "r"(saddr), "l"(g));
}
#define CP_COMMIT  asm volatile("cp.async.commit_group;" ::: "memory")
#define CP_WAIT(n) asm volatile("cp.async.wait_group %0;" :: "n"(n) : "memory")

__device__ __forceinline__ void ldmatrix_x4(uint32_t& r0, uint32_t& r1, uint32_t& r2,
                                            uint32_t& r3, uint32_t addr) {
    asm volatile("ldmatrix.sync.aligned.m8n8.x4.shared.b16 {%0,%1,%2,%3}, [%4];"
                 : "=r"(r0), "=r"(r1), "=r"(r2), "=r"(r3) : "r"(addr));
}
__device__ __forceinline__ void ldmatrix_x4_trans(uint32_t& r0, uint32_t& r1, uint32_t& r2,
                                                  uint32_t& r3, uint32_t addr) {
    asm volatile("ldmatrix.sync.aligned.m8n8.x4.trans.shared.b16 {%0,%1,%2,%3}, [%4];"
                 : "=r"(r0), "=r"(r1), "=r"(r2), "=r"(r3) : "r"(addr));
}
__device__ __forceinline__ void mma_bf16(float* c, uint32_t a0, uint32_t a1, uint32_t a2,
                                         uint32_t a3, uint32_t b0, uint32_t b1) {
    asm volatile(
        "mma.sync.aligned.m16n8k16.row.col.f32.bf16.bf16.f32 "
        "{%0,%1,%2,%3}, {%4,%5,%6,%7}, {%8,%9}, {%0,%1,%2,%3};"
        : "+f"(c[0]), "+f"(c[1]), "+f"(c[2]), "+f"(c[3])
        : "r"(a0), "r"(a1), "r"(a2), "r"(a3), "r"(b0), "r"(b1));
}
// vector fp32 reduction (sm_90+ baseline PTX feature)
__device__ __forceinline__ void red_add_v2(float* addr, float a, float b) {
    asm volatile("red.global.add.v2.f32 [%0], {%1, %2};"
                 :: "l"(addr), "f"(a), "f"(b) : "memory");
}

__device__ __forceinline__ void split2(float x, __nv_bfloat16& hi, __nv_bfloat16& lo) {
    hi = __float2bfloat16(x);
    lo = __float2bfloat16(x - __bfloat162float(hi));
}
union BF2 { __nv_bfloat16 h[2]; uint32_t u; };

// Stage maps: logical stage s (0..11) -> physical 64-col chunk in [hi|lo] storage.
// Pairing: s 0-3 hi*hi, 4-7 lo*hi, 8-11 hi*lo.
__device__ __forceinline__ int amap(int s) { return s < 8 ? s : s - 8; }
__device__ __forceinline__ int bmap(int s) { return s < 4 ? s : s - 4; }

// ======================= warp-MMA mainloop (128x128 tile) =======================
// 3-stage cp.async ring, ONE __syncthreads per stage.
#define NSTAGE  12
#define STAGE_BYTES 32768
#define SMEM_MMA (3 * STAGE_BYTES)

__device__ __forceinline__ void load_stage(uint32_t sbase,
    const __nv_bfloat16* __restrict__ A, const __nv_bfloat16* __restrict__ B,
    int s, int tid)
{
    const __nv_bfloat16* Ak = A + amap(s) * 64;
    const __nv_bfloat16* Bk = B + bmap(s) * 64;
#pragma unroll
    for (int i = 0; i < 4; ++i) {
        const int idx = tid + i * 256;            // 0..1023 16B chunks
        const int r = idx >> 3, c = idx & 7;
        const uint32_t off = SMEM_SWIZZLE_128B((uint32_t)(r * 128 + c * 16));
        cp_async16(sbase + off, Ak + (size_t)r * KS + c * 8);
        cp_async16(sbase + 16384 + off, Bk + (size_t)r * KS + c * 8);
    }
}

__device__ __forceinline__ void warp_mma_main(
    const __nv_bfloat16* __restrict__ A, const __nv_bfloat16* __restrict__ B,
    uint32_t smem_base, int tid, float acc[4][4][4])
{
    const int wid = tid >> 5, lane = tid & 31;
    const int mw = (wid >> 2) * 64, nw = (wid & 3) * 32;

    load_stage(smem_base + 0 * STAGE_BYTES, A, B, 0, tid); CP_COMMIT;
    load_stage(smem_base + 1 * STAGE_BYTES, A, B, 1, tid); CP_COMMIT;

    for (int s = 0; s < NSTAGE; ++s) {
        CP_WAIT(1);            // stage s group complete (groups retire in order)
        __syncthreads();       // publish stage s; fences reuse of buf[(s+2)%3]
        if (s + 2 < NSTAGE)
            load_stage(smem_base + ((s + 2) % 3) * STAGE_BYTES, A, B, s + 2, tid);
        CP_COMMIT;

        const uint32_t sA = smem_base + (s % 3) * STAGE_BYTES;
        const uint32_t sB = sA + 16384;
#pragma unroll
        for (int kk = 0; kk < 64; kk += 16) {
            uint32_t a[4][4], b[4][2];
#pragma unroll
            for (int mf = 0; mf < 4; ++mf) {
                const uint32_t off = SMEM_SWIZZLE_128B((uint32_t)(
                    (mw + mf * 16 + (lane & 15)) * 128 + kk * 2 + ((lane >> 4) << 4)));
                ldmatrix_x4(a[mf][0], a[mf][1], a[mf][2], a[mf][3], sA + off);
            }
#pragma unroll
            for (int nb = 0; nb < 2; ++nb) {
                const int row = nw + nb * 16 + ((lane >> 4) & 1) * 8 + (lane & 7);
                const int kof = kk * 2 + (((lane >> 3) & 1) << 4);
                const uint32_t off = SMEM_SWIZZLE_128B((uint32_t)(row * 128 + kof));
                ldmatrix_x4(b[nb * 2][0], b[nb * 2][1], b[nb * 2 + 1][0], b[nb * 2 + 1][1],
                            sB + off);
            }
#pragma unroll
            for (int mf = 0; mf < 4; ++mf)
#pragma unroll
                for (int nf = 0; nf < 4; ++nf)
                    mma_bf16(acc[mf][nf], a[mf][0], a[mf][1], a[mf][2], a[mf][3],
                             b[nf][0], b[nf][1]);
        }
    }
    __syncthreads();   // all warps done with ring before caller reuses smem
}

// ======================= fused rel + att-score kernel =======================
#define R_PITCH  272          // 128 cols bf16 (256B) + 16B pad
#define P_PITCH  144          // 64 cols bf16 (128B) + 16B pad
#define RH_OFF   0
#define RL_OFF   34816
#define PJH_OFF  69632
#define PJL_OFF  88064
#define SMEM_FUSED 106496     // >= 3*STAGE_BYTES mainloop ring

__global__ void __launch_bounds__(256, 2) rel_fused_kernel(
    const __nv_bfloat16* __restrict__ Qw2, const __nv_bfloat16* __restrict__ K2,
    const __nv_bfloat16* __restrict__ kph, const __nv_bfloat16* __restrict__ kpl,
    const __nv_bfloat16* __restrict__ qph, const __nv_bfloat16* __restrict__ qpl,
    float* __restrict__ accQ, float* __restrict__ accK)
{
    extern __shared__ char smem[];
    const uint32_t sb = smem_to_u32(smem);
    const int tid = threadIdx.x, wid = tid >> 5, lane = tid & 31;
    const int mt = blockIdx.x, nt = blockIdx.y, b = blockIdx.z;
    const int m0 = mt * 128, n0 = nt * 128;

    float acc[4][4][4] = {};
    warp_mma_main(Qw2 + ((size_t)b * LN + m0) * KS,
                  K2  + ((size_t)b * LN + n0) * KS, sb, tid, acc);

    // prefetch kp hi/lo tiles (rows n0..n0+127) while storing rel to smem
    {
        const __nv_bfloat16* kh = kph + ((size_t)b * LN + n0) * AN;
        const __nv_bfloat16* kl = kpl + ((size_t)b * LN + n0) * AN;
#pragma unroll
        for (int i = 0; i < 4; ++i) {
            const int idx = tid + i * 256, r = idx >> 3, c = idx & 7;
            cp_async16(sb + PJH_OFF + r * P_PITCH + c * 16, kh + (size_t)r * AN + c * 8);
            cp_async16(sb + PJL_OFF + r * P_PITCH + c * 16, kl + (size_t)r * AN + c * 8);
        }
        CP_COMMIT;
    }

    // tanh + hi/lo split -> smem rel tiles
    const int mw = (wid >> 2) * 64, nw = (wid & 3) * 32;
    const int lr = lane >> 2, lc = (lane & 3) * 2;
#pragma unroll
    for (int mf = 0; mf < 4; ++mf)
#pragma unroll
        for (int nf = 0; nf < 4; ++nf)
#pragma unroll
            for (int p = 0; p < 2; ++p) {
                const int rr = mw + mf * 16 + lr + p * 8;
                const int cc = nw + nf * 8 + lc;
                BF2 H, L;
                split2(tanhf(acc[mf][nf][2 * p + 0]), H.h[0], L.h[0]);
                split2(tanhf(acc[mf][nf][2 * p + 1]), H.h[1], L.h[1]);
                *(uint32_t*)(smem + RH_OFF + rr * R_PITCH + cc * 2) = H.u;
                *(uint32_t*)(smem + RL_OFF + rr * R_PITCH + cc * 2) = L.u;
            }
    CP_WAIT(0);
    __syncthreads();

    // ---- C2[m][a] = sum_n rel[m][n] * kp[n0+n][a]
    // 3-term split with frags loaded ONCE per kk: aH*bH + aL*bH + aH*bL
    float c2[8][4] = {};
#pragma unroll
    for (int kk = 0; kk < 128; kk += 16) {
        uint32_t aH0, aH1, aH2, aH3, aL0, aL1, aL2, aL3;
        const uint32_t aoff = (16 * wid + (lane & 15)) * R_PITCH
                            + (kk + ((lane >> 4) << 3)) * 2;
        ldmatrix_x4(aH0, aH1, aH2, aH3, sb + RH_OFF + aoff);
        ldmatrix_x4(aL0, aL1, aL2, aL3, sb + RL_OFF + aoff);
#pragma unroll
        for (int ab = 0; ab < 4; ++ab) {
            uint32_t h0, h1, h2, h3, l0, l1, l2, l3;
            const uint32_t boff = (kk + (lane & 15)) * P_PITCH
                                + (ab * 16 + ((lane >> 4) << 3)) * 2;
            ldmatrix_x4_trans(h0, h1, h2, h3, sb + PJH_OFF + boff);
            ldmatrix_x4_trans(l0, l1, l2, l3, sb + PJL_OFF + boff);
            mma_bf16(c2[2 * ab],     aH0, aH1, aH2, aH3, h0, h1);
            mma_bf16(c2[2 * ab],     aL0, aL1, aL2, aL3, h0, h1);
            mma_bf16(c2[2 * ab],     aH0, aH1, aH2, aH3, l0, l1);
            mma_bf16(c2[2 * ab + 1], aH0, aH1, aH2, aH3, h2, h3);
            mma_bf16(c2[2 * ab + 1], aL0, aL1, aL2, aL3, h2, h3);
            mma_bf16(c2[2 * ab + 1], aH0, aH1, aH2, aH3, l2, l3);
        }
    }
    {
        float* base = accQ + ((size_t)b * LN + m0 + 16 * wid) * AN;
#pragma unroll
        for (int j = 0; j < 8; ++j) {
            const int col = j * 8 + lc;
            red_add_v2(base + (size_t)lr * AN + col,       c2[j][0], c2[j][1]);
            red_add_v2(base + (size_t)(lr + 8) * AN + col, c2[j][2], c2[j][3]);
        }
    }
    __syncthreads();   // all warps done reading kp tiles

    // load qp hi/lo tiles (rows m0..m0+127) into same region
    {
        const __nv_bfloat16* qh = qph + ((size_t)b * LN + m0) * AN;
        const __nv_bfloat16* ql = qpl + ((size_t)b * LN + m0) * AN;
#pragma unroll
        for (int i = 0; i < 4; ++i) {
            const int idx = tid + i * 256, r = idx >> 3, c = idx & 7;
            cp_async16(sb + PJH_OFF + r * P_PITCH + c * 16, qh + (size_t)r * AN + c * 8);
            cp_async16(sb + PJL_OFF + r * P_PITCH + c * 16, ql + (size_t)r * AN + c * 8);
        }
        CP_COMMIT; CP_WAIT(0);
    }
    __syncthreads();

    // ---- C3[n][a] = sum_m rel[m][n] * qp[m0+m][a]  (A = rel^T via ldmatrix.trans)
    float c3[8][4] = {};
    const int g = lane >> 3;
#pragma unroll
    for (int kk = 0; kk < 128; kk += 16) {
        uint32_t aH0, aH1, aH2, aH3, aL0, aL1, aL2, aL3;
        const uint32_t aoff = (kk + ((g >> 1) << 3) + (lane & 7)) * R_PITCH
                            + (16 * wid + ((g & 1) << 3)) * 2;
        ldmatrix_x4_trans(aH0, aH1, aH2, aH3, sb + RH_OFF + aoff);
        ldmatrix_x4_trans(aL0, aL1, aL2, aL3, sb + RL_OFF + aoff);
#pragma unroll
        for (int ab = 0; ab < 4; ++ab) {
            uint32_t h0, h1, h2, h3, l0, l1, l2, l3;
            const uint32_t boff = (kk + (lane & 15)) * P_PITCH
                                + (ab * 16 + ((lane >> 4) << 3)) * 2;
            ldmatrix_x4_trans(h0, h1, h2, h3, sb + PJH_OFF + boff);
            ldmatrix_x4_trans(l0, l1, l2, l3, sb + PJL_OFF + boff);
            mma_bf16(c3[2 * ab],     aH0, aH1, aH2, aH3, h0, h1);
            mma_bf16(c3[2 * ab],     aL0, aL1, aL2, aL3, h0, h1);
            mma_bf16(c3[2 * ab],     aH0, aH1, aH2, aH3, l0, l1);
            mma_bf16(c3[2 * ab + 1], aH0, aH1, aH2, aH3, h2, h3);
            mma_bf16(c3[2 * ab + 1], aL0, aL1, aL2, aL3, h2, h3);
            mma_bf16(c3[2 * ab + 1], aH0, aH1, aH2, aH3, l2, l3);
        }
    }
    {
        float* base = accK + ((size_t)b * LN + n0 + 16 * wid) * AN;
#pragma unroll
        for (int j = 0; j < 8; ++j) {
            const int col = j * 8 + lc;
            red_add_v2(base + (size_t)lr * AN + col,       c3[j][0], c3[j][1]);
            red_add_v2(base + (size_t)(lr + 8) * AN + col, c3[j][2], c3[j][3]);
        }
    }
}

// ======================= slim Qw kernel (CTA 64m x 128n, 3 CTA/SM) ==========
// Stage = A(8KB, 64 rows) + B(16KB, 128 rows) = 24KB; 3-stage ring.
// 8 warps as 2m x 4n, warp tile 32x32 -> acc[2][4][4] = 32 regs.
#define QWS_STAGE 24576
#define SMEM_QWS  (3 * QWS_STAGE)

__device__ __forceinline__ void load_stage_qws(uint32_t sbase,
    const __nv_bfloat16* __restrict__ A, const __nv_bfloat16* __restrict__ B,
    int s, int tid)
{
    const __nv_bfloat16* Ak = A + amap(s) * 64;
    const __nv_bfloat16* Bk = B + bmap(s) * 64;
#pragma unroll
    for (int i = 0; i < 2; ++i) {
        const int idx = tid + i * 256;            // 512 chunks: A 64 rows x 8
        const int r = idx >> 3, c = idx & 7;
        const uint32_t off = SMEM_SWIZZLE_128B((uint32_t)(r * 128 + c * 16));
        cp_async16(sbase + off, Ak + (size_t)r * KS + c * 8);
    }
#pragma unroll
    for (int i = 0; i < 4; ++i) {
        const int idx = tid + i * 256;            // 1024 chunks: B 128 rows x 8
        const int r = idx >> 3, c = idx & 7;
        const uint32_t off = SMEM_SWIZZLE_128B((uint32_t)(r * 128 + c * 16));
        cp_async16(sbase + 8192 + off, Bk + (size_t)r * KS + c * 8);
    }
}

__global__ void __launch_bounds__(256, 3) qw_slim_kernel(
    const __nv_bfloat16* __restrict__ Q2, const __nv_bfloat16* __restrict__ W2t,
    __nv_bfloat16* __restrict__ Qw2)
{
    extern __shared__ char smem[];
    const uint32_t sb = smem_to_u32(smem);
    const int tid = threadIdx.x, wid = tid >> 5, lane = tid & 31;
    const int m0 = blockIdx.y * 64, n0 = blockIdx.x * 128;   // n fastest
    const __nv_bfloat16* A = Q2  + (size_t)m0 * KS;
    const __nv_bfloat16* B = W2t + (size_t)n0 * KS;

    const int mw = (wid >> 2) * 32, nw = (wid & 3) * 32;

    float acc[2][4][4] = {};
    load_stage_qws(sb + 0 * QWS_STAGE, A, B, 0, tid); CP_COMMIT;
    load_stage_qws(sb + 1 * QWS_STAGE, A, B, 1, tid); CP_COMMIT;

    for (int s = 0; s < NSTAGE; ++s) {
        CP_WAIT(1);
        __syncthreads();
        if (s + 2 < NSTAGE)
            load_stage_qws(sb + ((s + 2) % 3) * QWS_STAGE, A, B, s + 2, tid);
        CP_COMMIT;

        const uint32_t sA = sb + (s % 3) * QWS_STAGE;
        const uint32_t sB = sA + 8192;
#pragma unroll
        for (int kk = 0; kk < 64; kk += 16) {
            uint32_t a[2][4], b[4][2];
#pragma unroll
            for (int mf = 0; mf < 2; ++mf) {
                const uint32_t off = SMEM_SWIZZLE_128B((uint32_t)(
                    (mw + mf * 16 + (lane & 15)) * 128 + kk * 2 + ((lane >> 4) << 4)));
                ldmatrix_x4(a[mf][0], a[mf][1], a[mf][2], a[mf][3], sA + off);
            }
#pragma unroll
            for (int nb = 0; nb < 2; ++nb) {
                const int row = nw + nb * 16 + ((lane >> 4) & 1) * 8 + (lane & 7);
                const int kof = kk * 2 + (((lane >> 3) & 1) << 4);
                const uint32_t off = SMEM_SWIZZLE_128B((uint32_t)(row * 128 + kof));
                ldmatrix_x4(b[nb * 2][0], b[nb * 2][1], b[nb * 2 + 1][0], b[nb * 2 + 1][1],
                            sB + off);
            }
#pragma unroll
            for (int mf = 0; mf < 2; ++mf)
#pragma unroll
                for (int nf = 0; nf < 4; ++nf)
                    mma_bf16(acc[mf][nf], a[mf][0], a[mf][1], a[mf][2], a[mf][3],
                             b[nf][0], b[nf][1]);
        }
    }

    const int lr = lane >> 2, lc = (lane & 3) * 2;
#pragma unroll
    for (int mf = 0; mf < 2; ++mf) {
#pragma unroll
        for (int nf = 0; nf < 4; ++nf) {
            const int col = n0 + nw + nf * 8 + lc;
#pragma unroll
            for (int p = 0; p < 2; ++p) {
                const int row = m0 + mw + mf * 16 + lr + p * 8;
                BF2 H, L;
                split2(acc[mf][nf][2 * p + 0], H.h[0], L.h[0]);
                split2(acc[mf][nf][2 * p + 1], H.h[1], L.h[1]);
                __nv_bfloat16* o = Qw2 + (size_t)row * KS + col;
                *(uint32_t*)(o)       = H.u;
                *(uint32_t*)(o + 256) = L.u;
            }
        }
    }
}

// ======================= slim projection kernel (N=64) ======================
// 3-stage ring. Stage = A(16KB) + W(8KB) = 24KB.
#define SLIM_STAGE 24576
#define SMEM_SLIM  (3 * SLIM_STAGE)

__device__ __forceinline__ void load_stage_slim(uint32_t sbase,
    const __nv_bfloat16* __restrict__ A, const __nv_bfloat16* __restrict__ W,
    int s, int tid)
{
    const __nv_bfloat16* Ak = A + amap(s) * 64;
    const __nv_bfloat16* Wk = W + bmap(s) * 64;
#pragma unroll
    for (int i = 0; i < 4; ++i) {
        const int idx = tid + i * 256;            // 1024 chunks: A 128 rows x 8
        const int r = idx >> 3, c = idx & 7;
        const uint32_t off = SMEM_SWIZZLE_128B((uint32_t)(r * 128 + c * 16));
        cp_async16(sbase + off, Ak + (size_t)r * KS + c * 8);
    }
#pragma unroll
    for (int i = 0; i < 2; ++i) {
        const int idx = tid + i * 256;            // 512 chunks: W 64 rows x 8
        const int r = idx >> 3, c = idx & 7;
        const uint32_t off = SMEM_SWIZZLE_128B((uint32_t)(r * 128 + c * 16));
        cp_async16(sbase + 16384 + off, Wk + (size_t)r * KS + c * 8);
    }
}

__global__ void __launch_bounds__(256, 3) proj_slim_kernel(
    const __nv_bfloat16* __restrict__ Q2, const __nv_bfloat16* __restrict__ K2,
    const __nv_bfloat16* __restrict__ Wp2t,
    float* __restrict__ accQ, float* __restrict__ accK,
    __nv_bfloat16* __restrict__ qph, __nv_bfloat16* __restrict__ qpl,
    __nv_bfloat16* __restrict__ kph, __nv_bfloat16* __restrict__ kpl)
{
    extern __shared__ char smem[];
    const uint32_t sb = smem_to_u32(smem);
    const int tid = threadIdx.x, wid = tid >> 5, lane = tid & 31;
    const int side = blockIdx.y;
    const int m0 = blockIdx.x * 128;
    const __nv_bfloat16* A = (side ? K2 : Q2) + (size_t)m0 * KS;
    const __nv_bfloat16* W = Wp2t + (size_t)side * 64 * KS;
    float* pf = side ? accK : accQ;
    __nv_bfloat16* ph = side ? kph : qph;
    __nv_bfloat16* pl = side ? kpl : qpl;

    const int mw = (wid >> 1) * 32, nw = (wid & 1) * 32;

    float acc[2][4][4] = {};
    load_stage_slim(sb + 0 * SLIM_STAGE, A, W, 0, tid); CP_COMMIT;
    load_stage_slim(sb + 1 * SLIM_STAGE, A, W, 1, tid); CP_COMMIT;

    for (int s = 0; s < NSTAGE; ++s) {
        CP_WAIT(1);
        __syncthreads();
        if (s + 2 < NSTAGE)
            load_stage_slim(sb + ((s + 2) % 3) * SLIM_STAGE, A, W, s + 2, tid);
        CP_COMMIT;

        const uint32_t sA = sb + (s % 3) * SLIM_STAGE;
        const uint32_t sW = sA + 16384;
#pragma unroll
        for (int kk = 0; kk < 64; kk += 16) {
            uint32_t a[2][4], b[4][2];
#pragma unroll
            for (int mf = 0; mf < 2; ++mf) {
                const uint32_t off = SMEM_SWIZZLE_128B((uint32_t)(
                    (mw + mf * 16 + (lane & 15)) * 128 + kk * 2 + ((lane >> 4) << 4)));
                ldmatrix_x4(a[mf][0], a[mf][1], a[mf][2], a[mf][3], sA + off);
            }
#pragma unroll
            for (int nb = 0; nb < 2; ++nb) {
                const int row = nw + nb * 16 + ((lane >> 4) & 1) * 8 + (lane & 7);
                const int kof = kk * 2 + (((lane >> 3) & 1) << 4);
                const uint32_t off = SMEM_SWIZZLE_128B((uint32_t)(row * 128 + kof));
                ldmatrix_x4(b[nb * 2][0], b[nb * 2][1], b[nb * 2 + 1][0], b[nb * 2 + 1][1],
                            sW + off);
            }
#pragma unroll
            for (int mf = 0; mf < 2; ++mf)
#pragma unroll
                for (int nf = 0; nf < 4; ++nf)
                    mma_bf16(acc[mf][nf], a[mf][0], a[mf][1], a[mf][2], a[mf][3],
                             b[nf][0], b[nf][1]);
        }
    }

    const int lr = lane >> 2, lc = (lane & 3) * 2;
#pragma unroll
    for (int mf = 0; mf < 2; ++mf) {
#pragma unroll
        for (int nf = 0; nf < 4; ++nf) {
            const int col = nw + nf * 8 + lc;
#pragma unroll
            for (int p = 0; p < 2; ++p) {
                const int row = m0 + mw + mf * 16 + lr + p * 8;
                const float v0 = acc[mf][nf][2 * p + 0];
                const float v1 = acc[mf][nf][2 * p + 1];
                *(float2*)(pf + (size_t)row * AN + col) = make_float2(v0, v1);
                BF2 H, L;
                split2(v0, H.h[0], L.h[0]);
                split2(v1, H.h[1], L.h[1]);
                *(uint32_t*)(ph + (size_t)row * AN + col) = H.u;
                *(uint32_t*)(pl + (size_t)row * AN + col) = L.u;
            }
        }
    }
}

// ======================= split / prep kernels =======================
// 8 elems per thread, uint4 (16B) stores
__global__ void __launch_bounds__(256) split_kernel(
    const float* __restrict__ Q, const float* __restrict__ Kmat,
    __nv_bfloat16* __restrict__ Q2, __nv_bfloat16* __restrict__ K2)
{
    const int sel = blockIdx.y;
    const float* src = sel ? Kmat : Q;
    __nv_bfloat16* dst = sel ? K2 : Q2;
    const size_t i8 = (size_t)blockIdx.x * 256 + threadIdx.x;   // per 8 elems
    const size_t row = i8 >> 5;
    const int c = (int)(i8 & 31) * 8;
    const float4 v0 = ((const float4*)src)[i8 * 2];
    const float4 v1 = ((const float4*)src)[i8 * 2 + 1];
    union { __nv_bfloat16 b[8]; uint4 u; } h, l;
    split2(v0.x, h.b[0], l.b[0]); split2(v0.y, h.b[1], l.b[1]);
    split2(v0.z, h.b[2], l.b[2]); split2(v0.w, h.b[3], l.b[3]);
    split2(v1.x, h.b[4], l.b[4]); split2(v1.y, h.b[5], l.b[5]);
    split2(v1.z, h.b[6], l.b[6]); split2(v1.w, h.b[7], l.b[7]);
    __nv_bfloat16* o = dst + row * KS + c;
    *(uint4*)(o)       = h.u;
    *(uint4*)(o + 256) = l.u;
}

__global__ void __launch_bounds__(256) prep_w2t(
    const float* __restrict__ Wrel, __nv_bfloat16* __restrict__ W2t)
{
    const int idx = blockIdx.x * 256 + threadIdx.x;   // 65536
    const int d = idx >> 8, n = idx & 255;
    __nv_bfloat16 hi, lo;
    split2(Wrel[d * 256 + n], hi, lo);
    W2t[(size_t)n * KS + d]       = hi;
    W2t[(size_t)n * KS + 256 + d] = lo;
}

__global__ void __launch_bounds__(256) prep_wp(
    const float* __restrict__ Wq, const float* __restrict__ Wk,
    __nv_bfloat16* __restrict__ Wp2t)
{
    const int idx = blockIdx.x * 256 + threadIdx.x;   // 32768
    const int side = idx >> 14;
    const int d = (idx >> 6) & 255, a = idx & 63;
    const float* W = side ? Wk : Wq;
    __nv_bfloat16 hi, lo;
    split2(W[d * 64 + a], hi, lo);
    __nv_bfloat16* slab = Wp2t + (size_t)side * 64 * KS;
    slab[(size_t)a * KS + d]       = hi;
    slab[(size_t)a * KS + 256 + d] = lo;
}

// ======================= tanh + dot reduce (reads accumulators) =============
__global__ void __launch_bounds__(256) att_reduce_kernel(
    const float* __restrict__ accQ, const float* __restrict__ accK,
    const float* __restrict__ Wqa, const float* __restrict__ Wka,
    float* __restrict__ lq, float* __restrict__ lk)
{
    const int side = blockIdx.y;
    const int wid = threadIdx.x >> 5, lane = threadIdx.x & 31;
    const size_t gm = (size_t)blockIdx.x * 8 + wid;   // b*LN + m
    const float* acc = side ? accK : accQ;
    const float* w   = side ? Wka  : Wqa;
    float* out       = side ? lk   : lq;

    float s = 0.f;
#pragma unroll
    for (int h = 0; h < 2; ++h) {
        const int a = lane + h * 32;
        s += tanhf(acc[gm * AN + a]) * w[a];
    }
#pragma unroll
    for (int o = 16; o; o >>= 1) s += __shfl_xor_sync(0xFFFFFFFFu, s, o);
    if (lane == 0) out[gm] = s;
}

// ============================================================================
__global__ void __launch_bounds__(512) softmax_kernel(
    const float* __restrict__ lq, const float* __restrict__ lk,
    float* __restrict__ out)
{
    __shared__ float red[512];
    const int b = blockIdx.x, sel = blockIdx.y, t = threadIdx.x;
    const float* l = (sel ? lk : lq) + (size_t)b * LN;
    float* o = out + (sel ? OFF_KW : OFF_QW) + (size_t)b * LN;

    float v = l[t];
    red[t] = v; __syncthreads();
    for (int s = 256; s > 0; s >>= 1) {
        if (t < s) red[t] = fmaxf(red[t], red[t + s]);
        __syncthreads();
    }
    const float mx = red[0];
    __syncthreads();
    const float e = expf(v - mx);
    red[t] = e; __syncthreads();
    for (int s = 256; s > 0; s >>= 1) {
        if (t < s) red[t] += red[t + s];
        __syncthreads();
    }
    o[t] = e / red[0];
}

// weighted outputs from compact bf16 [hi|lo] (exact to ~1e-5): q = hi + lo
__global__ void __launch_bounds__(256) scale_kernel(
    const __nv_bfloat16* __restrict__ Q2, const __nv_bfloat16* __restrict__ K2,
    float* __restrict__ out)
{
    const int sel = blockIdx.y;
    const size_t i4 = (size_t)blockIdx.x * 256 + threadIdx.x;
    const __nv_bfloat16* src = sel ? K2 : Q2;
    const float* w = out + (sel ? OFF_KW : OFF_QW);
    float4* dst = (float4*)(out + (sel ? OFF_WK : OFF_WQ));

    const size_t e = i4 * 4;
    const size_t row = e >> 8;            // b*LN + l
    const int c = (int)(e & 255);
    const float s = w[row];

    const __nv_bfloat16* p = src + row * KS + c;
    union { __nv_bfloat16 b[4]; uint2 u; } h, l;
    h.u = *(const uint2*)(p);
    l.u = *(const uint2*)(p + 256);
    float4 v;
    v.x = (__bfloat162float(h.b[0]) + __bfloat162float(l.b[0])) * s;
    v.y = (__bfloat162float(h.b[1]) + __bfloat162float(l.b[1])) * s;
    v.z = (__bfloat162float(h.b[2]) + __bfloat162float(l.b[2])) * s;
    v.w = (__bfloat162float(h.b[3]) + __bfloat162float(l.b[3])) * s;
    dst[i4] = v;
}

// ============================================================================
extern "C" void kernel_launch(void* const* d_in, const int* in_sizes, int n_in,
                              void* d_out, int out_size)
{
    (void)in_sizes; (void)n_in; (void)out_size;
    const float* Q    = (const float*)d_in[0];
    const float* Km   = (const float*)d_in[1];
    const float* Wrel = (const float*)d_in[2];
    const float* Wq   = (const float*)d_in[3];
    const float* Wk   = (const float*)d_in[4];
    const float* Wqa  = (const float*)d_in[5];
    const float* Wka  = (const float*)d_in[6];
    float* out = (float*)d_out;

    __nv_bfloat16 *q2, *k2, *qw2, *w2t, *wp2t, *qph, *qpl, *kph, *kpl;
    float *aQ, *aK, *lq, *lk;
    cudaGetSymbolAddress((void**)&q2,   g_Q2);
    cudaGetSymbolAddress((void**)&k2,   g_K2);
    cudaGetSymbolAddress((void**)&qw2,  g_Qw2);
    cudaGetSymbolAddress((void**)&w2t,  g_W2t);
    cudaGetSymbolAddress((void**)&wp2t, g_Wp2t);
    cudaGetSymbolAddress((void**)&aQ,   g_accQ);
    cudaGetSymbolAddress((void**)&aK,   g_accK);
    cudaGetSymbolAddress((void**)&qph,  g_qph);
    cudaGetSymbolAddress((void**)&qpl,  g_qpl);
    cudaGetSymbolAddress((void**)&kph,  g_kph);
    cudaGetSymbolAddress((void**)&kpl,  g_kpl);
    cudaGetSymbolAddress((void**)&lq,   g_logit_q);
    cudaGetSymbolAddress((void**)&lk,   g_logit_k);

    cudaFuncSetAttribute(qw_slim_kernel,   cudaFuncAttributeMaxDynamicSharedMemorySize, SMEM_QWS);
    cudaFuncSetAttribute(proj_slim_kernel, cudaFuncAttributeMaxDynamicSharedMemorySize, SMEM_SLIM);
    cudaFuncSetAttribute(rel_fused_kernel, cudaFuncAttributeMaxDynamicSharedMemorySize, SMEM_FUSED);

    const dim3 blk(256);
    // compact [hi|lo] splits of inputs + weight transposes
    split_kernel<<<dim3((BN * LN * DN) / 8 / 256, 2), blk>>>(Q, Km, q2, k2);
    prep_w2t<<<256, blk>>>(Wrel, w2t);
    prep_wp<<<128, blk>>>(Wq, Wk, wp2t);
    // projections -> accumulator base values + bf16 hi/lo copies
    proj_slim_kernel<<<dim3(512, 2), blk, SMEM_SLIM>>>(
        q2, k2, wp2t, aQ, aK, qph, qpl, kph, kpl);
    // Qw (slim 64x128 tiles, 3 CTA/SM; n fastest for Q2 L2 reuse)
    qw_slim_kernel<<<dim3(2, 1024), blk, SMEM_QWS>>>(q2, w2t, qw2);
    // fused rel + both score GEMMs -> vector REDs into accumulators
    rel_fused_kernel<<<dim3(4, 4, BN), blk, SMEM_FUSED>>>(qw2, k2, kph, kpl, qph, qpl, aQ, aK);
    // tanh + @W_att -> logits
    att_reduce_kernel<<<dim3(BN * LN / 8, 2), blk>>>(aQ, aK, Wqa, Wka, lq, lk);
    // softmax -> weights in d_out
    softmax_kernel<<<dim3(BN, 2), 512>>>(lq, lk, out);
    // weighted outputs from compact bf16
    scale_kernel<<<dim3((BN * LN * DN) / 4 / 256, 2), 256>>>(q2, k2, out);
}

// round 15
// speedup vs baseline: 1.0420x; 1.0150x over previous
#include <cuda_runtime.h>
#include <cuda_bf16.h>
#include <math.h>
#include <stdint.h>

// Problem dims
#define BN 128
#define LN 512
#define DN 256
#define AN 64
#define KS 512   // compact split storage: [hi | lo] x 256

// Output layout (concatenated, reference tuple order)
#define OFF_WQ  ((size_t)0)
#define OFF_WK  ((size_t)BN * LN * DN)
#define OFF_QW  ((size_t)2 * BN * LN * DN)
#define OFF_KW  (OFF_QW + (size_t)BN * LN)

// -------- scratch (device globals; no allocation allowed) --------
__device__ __nv_bfloat16 g_Q2 [(size_t)BN * LN * KS];    // [hi|lo] of Q
__device__ __nv_bfloat16 g_K2 [(size_t)BN * LN * KS];    // [hi|lo] of K
__device__ __nv_bfloat16 g_Qw2[(size_t)BN * LN * KS];    // [hi|lo] of Qw
__device__ __nv_bfloat16 g_W2t[(size_t)DN * KS];         // W_rel^T [hi|lo]
__device__ __nv_bfloat16 g_Wp2t[2 * 64 * KS];            // Wq^T / Wk^T [hi|lo]
__device__ float g_accQ[(size_t)BN * LN * AN];           // q_proj + rel@kp
__device__ float g_accK[(size_t)BN * LN * AN];           // k_proj + relT@qp
__device__ __nv_bfloat16 g_qph[(size_t)BN * LN * AN], g_qpl[(size_t)BN * LN * AN];
__device__ __nv_bfloat16 g_kph[(size_t)BN * LN * AN], g_kpl[(size_t)BN * LN * AN];
__device__ float g_logit_q[BN * LN];
__device__ float g_logit_k[BN * LN];

// ======================= helpers (baseline PTX only) =======================
__device__ __forceinline__ uint32_t smem_to_u32(const void* p) {
    uint32_t a;
    asm("{ .reg .u64 t; cvta.to.shared.u64 t, %1; cvt.u32.u64 %0, t; }" : "=r"(a) : "l"(p));
    return a;
}
#define SMEM_SWIZZLE_128B(o) ((o) ^ (((o) >> 3) & 0x70))

__device__ __forceinline__ void cp_async16(uint32_t saddr, const void* g) {
    asm volatile("cp.async.cg.shared.global [%0], [%1], 16;" :: "r"(saddr), "l"(g));
}
#define CP_COMMIT  asm volatile("cp.async.commit_group;" ::: "memory")
#define CP_WAIT(n) asm volatile("cp.async.wait_group %0;" :: "n"(n) : "memory")

__device__ __forceinline__ void ldmatrix_x4(uint32_t& r0, uint32_t& r1, uint32_t& r2,
                                            uint32_t& r3, uint32_t addr) {
    asm volatile("ldmatrix.sync.aligned.m8n8.x4.shared.b16 {%0,%1,%2,%3}, [%4];"
                 : "=r"(r0), "=r"(r1), "=r"(r2), "=r"(r3) : "r"(addr));
}
__device__ __forceinline__ void ldmatrix_x4_trans(uint32_t& r0, uint32_t& r1, uint32_t& r2,
                                                  uint32_t& r3, uint32_t addr) {
    asm volatile("ldmatrix.sync.aligned.m8n8.x4.trans.shared.b16 {%0,%1,%2,%3}, [%4];"
                 : "=r"(r0), "=r"(r1), "=r"(r2), "=r"(r3) : "r"(addr));
}
__device__ __forceinline__ void mma_bf16(float* c, uint32_t a0, uint32_t a1, uint32_t a2,
                                         uint32_t a3, uint32_t b0, uint32_t b1) {
    asm volatile(
        "mma.sync.aligned.m16n8k16.row.col.f32.bf16.bf16.f32 "
        "{%0,%1,%2,%3}, {%4,%5,%6,%7}, {%8,%9}, {%0,%1,%2,%3};"
        : "+f"(c[0]), "+f"(c[1]), "+f"(c[2]), "+f"(c[3])
        : "r"(a0), "r"(a1), "r"(a2), "r"(a3), "r"(b0), "r"(b1));
}
// vector fp32 reduction (sm_90+ baseline PTX feature)
__device__ __forceinline__ void red_add_v2(float* addr, float a, float b) {
    asm volatile("red.global.add.v2.f32 [%0], {%1, %2};"
                 :: "l"(addr), "f"(a), "f"(b) : "memory");
}

__device__ __forceinline__ void split2(float x, __nv_bfloat16& hi, __nv_bfloat16& lo) {
    hi = __float2bfloat16(x);
    lo = __float2bfloat16(x - __bfloat162float(hi));
}
union BF2 { __nv_bfloat16 h[2]; uint32_t u; };

// Stage maps for the 12-stage kernels (qw/proj): s 0-3 hi*hi, 4-7 lo*hi, 8-11 hi*lo.
__device__ __forceinline__ int amap(int s) { return s < 8 ? s : s - 8; }
__device__ __forceinline__ int bmap(int s) { return s < 4 ? s : s - 4; }

#define NSTAGE  12
#define STAGE_BYTES 32768

// ======================= fused rel + att-score kernel =======================
// Mainloop: chunk-set schedule. 4 chunks of 64 k-cols; per chunk TWO half-stage
// loads (hi: A-hi+B-hi, lo: A-lo+B-lo), ring of 3 x 32KB. Fragments loaded once
// per kk and reused across the 3 split terms (hh, lh, hl): LDSM halved vs the
// 12-stage schedule, gmem -33%, same MMA count.
#define R_PITCH  272          // 128 cols bf16 (256B) + 16B pad
#define P_PITCH  144          // 64 cols bf16 (128B) + 16B pad
#define RH_OFF   0
#define RL_OFF   34816
#define PJH_OFF  69632
#define PJL_OFF  88064
#define SMEM_FUSED 106496     // >= 3*STAGE_BYTES mainloop ring

__device__ __forceinline__ void load_half_rel(uint32_t sbase,
    const __nv_bfloat16* __restrict__ A, const __nv_bfloat16* __restrict__ B,
    int h, int tid)
{
    const int koff = (h & 1) * 256 + (h >> 1) * 64;   // hi/lo part + chunk
    const __nv_bfloat16* Ak = A + koff;
    const __nv_bfloat16* Bk = B + koff;
#pragma unroll
    for (int i = 0; i < 4; ++i) {
        const int idx = tid + i * 256;            // 0..1023 16B chunks
        const int r = idx >> 3, c = idx & 7;
        const uint32_t off = SMEM_SWIZZLE_128B((uint32_t)(r * 128 + c * 16));
        cp_async16(sbase + off, Ak + (size_t)r * KS + c * 8);
        cp_async16(sbase + 16384 + off, Bk + (size_t)r * KS + c * 8);
    }
}

__global__ void __launch_bounds__(256, 2) rel_fused_kernel(
    const __nv_bfloat16* __restrict__ Qw2, const __nv_bfloat16* __restrict__ K2,
    const __nv_bfloat16* __restrict__ kph, const __nv_bfloat16* __restrict__ kpl,
    const __nv_bfloat16* __restrict__ qph, const __nv_bfloat16* __restrict__ qpl,
    float* __restrict__ accQ, float* __restrict__ accK)
{
    extern __shared__ char smem[];
    const uint32_t sb = smem_to_u32(smem);
    const int tid = threadIdx.x, wid = tid >> 5, lane = tid & 31;
    const int mt = blockIdx.x, nt = blockIdx.y, b = blockIdx.z;
    const int m0 = mt * 128, n0 = nt * 128;
    const int mw = (wid >> 2) * 64, nw = (wid & 3) * 32;

    float acc[4][4][4] = {};
    {
        const __nv_bfloat16* A = Qw2 + ((size_t)b * LN + m0) * KS;
        const __nv_bfloat16* B = K2  + ((size_t)b * LN + n0) * KS;

        load_half_rel(sb + 0 * STAGE_BYTES, A, B, 0, tid); CP_COMMIT;
        load_half_rel(sb + 1 * STAGE_BYTES, A, B, 1, tid); CP_COMMIT;

        int sa = 0;   // ring slot of half 2c (hi)
        for (int c = 0; c < 4; ++c) {
            const int sl = (sa + 1 == 3) ? 0 : sa + 1;   // slot of half 2c+1 (lo)
            const int sp = (sl + 1 == 3) ? 0 : sl + 1;   // slot for half 2c+2
            if (c < 3) load_half_rel(sb + sp * STAGE_BYTES, A, B, 2 * c + 2, tid);
            CP_COMMIT;
            CP_WAIT(1);            // halves 2c, 2c+1 complete
            __syncthreads();

            const uint32_t bAh = sb + sa * STAGE_BYTES;
            const uint32_t bAl = sb + sl * STAGE_BYTES;
#pragma unroll
            for (int kk = 0; kk < 64; kk += 16) {
                uint32_t aH[4][4], bb[4][2];
#pragma unroll
                for (int mf = 0; mf < 4; ++mf) {
                    const uint32_t off = SMEM_SWIZZLE_128B((uint32_t)(
                        (mw + mf * 16 + (lane & 15)) * 128 + kk * 2 + ((lane >> 4) << 4)));
                    ldmatrix_x4(aH[mf][0], aH[mf][1], aH[mf][2], aH[mf][3], bAh + off);
                }
#pragma unroll
                for (int nb = 0; nb < 2; ++nb) {
                    const int row = nw + nb * 16 + ((lane >> 4) & 1) * 8 + (lane & 7);
                    const int kof = kk * 2 + (((lane >> 3) & 1) << 4);
                    const uint32_t off = SMEM_SWIZZLE_128B((uint32_t)(row * 128 + kof));
                    ldmatrix_x4(bb[nb * 2][0], bb[nb * 2][1], bb[nb * 2 + 1][0],
                                bb[nb * 2 + 1][1], bAh + 16384 + off);
                }
                // hh
#pragma unroll
                for (int mf = 0; mf < 4; ++mf)
#pragma unroll
                    for (int nf = 0; nf < 4; ++nf)
                        mma_bf16(acc[mf][nf], aH[mf][0], aH[mf][1], aH[mf][2], aH[mf][3],
                                 bb[nf][0], bb[nf][1]);
                // lh (aL scoped to bound register peak)
                {
                    uint32_t aL[4][4];
#pragma unroll
                    for (int mf = 0; mf < 4; ++mf) {
                        const uint32_t off = SMEM_SWIZZLE_128B((uint32_t)(
                            (mw + mf * 16 + (lane & 15)) * 128 + kk * 2 + ((lane >> 4) << 4)));
                        ldmatrix_x4(aL[mf][0], aL[mf][1], aL[mf][2], aL[mf][3], bAl + off);
                    }
#pragma unroll
                    for (int mf = 0; mf < 4; ++mf)
#pragma unroll
                        for (int nf = 0; nf < 4; ++nf)
                            mma_bf16(acc[mf][nf], aL[mf][0], aL[mf][1], aL[mf][2], aL[mf][3],
                                     bb[nf][0], bb[nf][1]);
                }
                // hl (reuse bb registers for B-lo)
#pragma unroll
                for (int nb = 0; nb < 2; ++nb) {
                    const int row = nw + nb * 16 + ((lane >> 4) & 1) * 8 + (lane & 7);
                    const int kof = kk * 2 + (((lane >> 3) & 1) << 4);
                    const uint32_t off = SMEM_SWIZZLE_128B((uint32_t)(row * 128 + kof));
                    ldmatrix_x4(bb[nb * 2][0], bb[nb * 2][1], bb[nb * 2 + 1][0],
                                bb[nb * 2 + 1][1], bAl + 16384 + off);
                }
#pragma unroll
                for (int mf = 0; mf < 4; ++mf)
#pragma unroll
                    for (int nf = 0; nf < 4; ++nf)
                        mma_bf16(acc[mf][nf], aH[mf][0], aH[mf][1], aH[mf][2], aH[mf][3],
                                 bb[nf][0], bb[nf][1]);
            }
            __syncthreads();   // ring slots free before reuse / before rel smem stores
            if (c < 3) { load_half_rel(sb + sa * STAGE_BYTES, A, B, 2 * c + 3, tid); CP_COMMIT; }
            sa = sp;
        }
    }

    // prefetch kp hi/lo tiles (rows n0..n0+127) while storing rel to smem
    {
        const __nv_bfloat16* kh = kph + ((size_t)b * LN + n0) * AN;
        const __nv_bfloat16* kl = kpl + ((size_t)b * LN + n0) * AN;
#pragma unroll
        for (int i = 0; i < 4; ++i) {
            const int idx = tid + i * 256, r = idx >> 3, c = idx & 7;
            cp_async16(sb + PJH_OFF + r * P_PITCH + c * 16, kh + (size_t)r * AN + c * 8);
            cp_async16(sb + PJL_OFF + r * P_PITCH + c * 16, kl + (size_t)r * AN + c * 8);
        }
        CP_COMMIT;
    }

    // tanh + hi/lo split -> smem rel tiles
    const int lr = lane >> 2, lc = (lane & 3) * 2;
#pragma unroll
    for (int mf = 0; mf < 4; ++mf)
#pragma unroll
        for (int nf = 0; nf < 4; ++nf)
#pragma unroll
            for (int p = 0; p < 2; ++p) {
                const int rr = mw + mf * 16 + lr + p * 8;
                const int cc = nw + nf * 8 + lc;
                BF2 H, L;
                split2(tanhf(acc[mf][nf][2 * p + 0]), H.h[0], L.h[0]);
                split2(tanhf(acc[mf][nf][2 * p + 1]), H.h[1], L.h[1]);
                *(uint32_t*)(smem + RH_OFF + rr * R_PITCH + cc * 2) = H.u;
                *(uint32_t*)(smem + RL_OFF + rr * R_PITCH + cc * 2) = L.u;
            }
    CP_WAIT(0);
    __syncthreads();

    // ---- C2[m][a] = sum_n rel[m][n] * kp[n0+n][a]
    float c2[8][4] = {};
#pragma unroll
    for (int kk = 0; kk < 128; kk += 16) {
        uint32_t aH0, aH1, aH2, aH3, aL0, aL1, aL2, aL3;
        const uint32_t aoff = (16 * wid + (lane & 15)) * R_PITCH
                            + (kk + ((lane >> 4) << 3)) * 2;
        ldmatrix_x4(aH0, aH1, aH2, aH3, sb + RH_OFF + aoff);
        ldmatrix_x4(aL0, aL1, aL2, aL3, sb + RL_OFF + aoff);
#pragma unroll
        for (int ab = 0; ab < 4; ++ab) {
            uint32_t h0, h1, h2, h3, l0, l1, l2, l3;
            const uint32_t boff = (kk + (lane & 15)) * P_PITCH
                                + (ab * 16 + ((lane >> 4) << 3)) * 2;
            ldmatrix_x4_trans(h0, h1, h2, h3, sb + PJH_OFF + boff);
            ldmatrix_x4_trans(l0, l1, l2, l3, sb + PJL_OFF + boff);
            mma_bf16(c2[2 * ab],     aH0, aH1, aH2, aH3, h0, h1);
            mma_bf16(c2[2 * ab],     aL0, aL1, aL2, aL3, h0, h1);
            mma_bf16(c2[2 * ab],     aH0, aH1, aH2, aH3, l0, l1);
            mma_bf16(c2[2 * ab + 1], aH0, aH1, aH2, aH3, h2, h3);
            mma_bf16(c2[2 * ab + 1], aL0, aL1, aL2, aL3, h2, h3);
            mma_bf16(c2[2 * ab + 1], aH0, aH1, aH2, aH3, l2, l3);
        }
    }
    {
        float* base = accQ + ((size_t)b * LN + m0 + 16 * wid) * AN;
#pragma unroll
        for (int j = 0; j < 8; ++j) {
            const int col = j * 8 + lc;
            red_add_v2(base + (size_t)lr * AN + col,       c2[j][0], c2[j][1]);
            red_add_v2(base + (size_t)(lr + 8) * AN + col, c2[j][2], c2[j][3]);
        }
    }
    __syncthreads();   // all warps done reading kp tiles

    // load qp hi/lo tiles (rows m0..m0+127) into same region
    {
        const __nv_bfloat16* qh = qph + ((size_t)b * LN + m0) * AN;
        const __nv_bfloat16* ql = qpl + ((size_t)b * LN + m0) * AN;
#pragma unroll
        for (int i = 0; i < 4; ++i) {
            const int idx = tid + i * 256, r = idx >> 3, c = idx & 7;
            cp_async16(sb + PJH_OFF + r * P_PITCH + c * 16, qh + (size_t)r * AN + c * 8);
            cp_async16(sb + PJL_OFF + r * P_PITCH + c * 16, ql + (size_t)r * AN + c * 8);
        }
        CP_COMMIT; CP_WAIT(0);
    }
    __syncthreads();

    // ---- C3[n][a] = sum_m rel[m][n] * qp[m0+m][a]  (A = rel^T via ldmatrix.trans)
    float c3[8][4] = {};
    const int g = lane >> 3;
#pragma unroll
    for (int kk = 0; kk < 128; kk += 16) {
        uint32_t aH0, aH1, aH2, aH3, aL0, aL1, aL2, aL3;
        const uint32_t aoff = (kk + ((g >> 1) << 3) + (lane & 7)) * R_PITCH
                            + (16 * wid + ((g & 1) << 3)) * 2;
        ldmatrix_x4_trans(aH0, aH1, aH2, aH3, sb + RH_OFF + aoff);
        ldmatrix_x4_trans(aL0, aL1, aL2, aL3, sb + RL_OFF + aoff);
#pragma unroll
        for (int ab = 0; ab < 4; ++ab) {
            uint32_t h0, h1, h2, h3, l0, l1, l2, l3;
            const uint32_t boff = (kk + (lane & 15)) * P_PITCH
                                + (ab * 16 + ((lane >> 4) << 3)) * 2;
            ldmatrix_x4_trans(h0, h1, h2, h3, sb + PJH_OFF + boff);
            ldmatrix_x4_trans(l0, l1, l2, l3, sb + PJL_OFF + boff);
            mma_bf16(c3[2 * ab],     aH0, aH1, aH2, aH3, h0, h1);
            mma_bf16(c3[2 * ab],     aL0, aL1, aL2, aL3, h0, h1);
            mma_bf16(c3[2 * ab],     aH0, aH1, aH2, aH3, l0, l1);
            mma_bf16(c3[2 * ab + 1], aH0, aH1, aH2, aH3, h2, h3);
            mma_bf16(c3[2 * ab + 1], aL0, aL1, aL2, aL3, h2, h3);
            mma_bf16(c3[2 * ab + 1], aH0, aH1, aH2, aH3, l2, l3);
        }
    }
    {
        float* base = accK + ((size_t)b * LN + n0 + 16 * wid) * AN;
#pragma unroll
        for (int j = 0; j < 8; ++j) {
            const int col = j * 8 + lc;
            red_add_v2(base + (size_t)lr * AN + col,       c3[j][0], c3[j][1]);
            red_add_v2(base + (size_t)(lr + 8) * AN + col, c3[j][2], c3[j][3]);
        }
    }
}

// ======================= slim Qw kernel (CTA 64m x 128n, 3 CTA/SM) ==========
#define QWS_STAGE 24576
#define SMEM_QWS  (3 * QWS_STAGE)

__device__ __forceinline__ void load_stage_qws(uint32_t sbase,
    const __nv_bfloat16* __restrict__ A, const __nv_bfloat16* __restrict__ B,
    int s, int tid)
{
    const __nv_bfloat16* Ak = A + amap(s) * 64;
    const __nv_bfloat16* Bk = B + bmap(s) * 64;
#pragma unroll
    for (int i = 0; i < 2; ++i) {
        const int idx = tid + i * 256;            // 512 chunks: A 64 rows x 8
        const int r = idx >> 3, c = idx & 7;
        const uint32_t off = SMEM_SWIZZLE_128B((uint32_t)(r * 128 + c * 16));
        cp_async16(sbase + off, Ak + (size_t)r * KS + c * 8);
    }
#pragma unroll
    for (int i = 0; i < 4; ++i) {
        const int idx = tid + i * 256;            // 1024 chunks: B 128 rows x 8
        const int r = idx >> 3, c = idx & 7;
        const uint32_t off = SMEM_SWIZZLE_128B((uint32_t)(r * 128 + c * 16));
        cp_async16(sbase + 8192 + off, Bk + (size_t)r * KS + c * 8);
    }
}

__global__ void __launch_bounds__(256, 3) qw_slim_kernel(
    const __nv_bfloat16* __restrict__ Q2, const __nv_bfloat16* __restrict__ W2t,
    __nv_bfloat16* __restrict__ Qw2)
{
    extern __shared__ char smem[];
    const uint32_t sb = smem_to_u32(smem);
    const int tid = threadIdx.x, wid = tid >> 5, lane = tid & 31;
    const int m0 = blockIdx.y * 64, n0 = blockIdx.x * 128;   // n fastest
    const __nv_bfloat16* A = Q2  + (size_t)m0 * KS;
    const __nv_bfloat16* B = W2t + (size_t)n0 * KS;

    const int mw = (wid >> 2) * 32, nw = (wid & 3) * 32;

    float acc[2][4][4] = {};
    load_stage_qws(sb + 0 * QWS_STAGE, A, B, 0, tid); CP_COMMIT;
    load_stage_qws(sb + 1 * QWS_STAGE, A, B, 1, tid); CP_COMMIT;

    for (int s = 0; s < NSTAGE; ++s) {
        CP_WAIT(1);
        __syncthreads();
        if (s + 2 < NSTAGE)
            load_stage_qws(sb + ((s + 2) % 3) * QWS_STAGE, A, B, s + 2, tid);
        CP_COMMIT;

        const uint32_t sA = sb + (s % 3) * QWS_STAGE;
        const uint32_t sB = sA + 8192;
#pragma unroll
        for (int kk = 0; kk < 64; kk += 16) {
            uint32_t a[2][4], b[4][2];
#pragma unroll
            for (int mf = 0; mf < 2; ++mf) {
                const uint32_t off = SMEM_SWIZZLE_128B((uint32_t)(
                    (mw + mf * 16 + (lane & 15)) * 128 + kk * 2 + ((lane >> 4) << 4)));
                ldmatrix_x4(a[mf][0], a[mf][1], a[mf][2], a[mf][3], sA + off);
            }
#pragma unroll
            for (int nb = 0; nb < 2; ++nb) {
                const int row = nw + nb * 16 + ((lane >> 4) & 1) * 8 + (lane & 7);
                const int kof = kk * 2 + (((lane >> 3) & 1) << 4);
                const uint32_t off = SMEM_SWIZZLE_128B((uint32_t)(row * 128 + kof));
                ldmatrix_x4(b[nb * 2][0], b[nb * 2][1], b[nb * 2 + 1][0], b[nb * 2 + 1][1],
                            sB + off);
            }
#pragma unroll
            for (int mf = 0; mf < 2; ++mf)
#pragma unroll
                for (int nf = 0; nf < 4; ++nf)
                    mma_bf16(acc[mf][nf], a[mf][0], a[mf][1], a[mf][2], a[mf][3],
                             b[nf][0], b[nf][1]);
        }
    }

    const int lr = lane >> 2, lc = (lane & 3) * 2;
#pragma unroll
    for (int mf = 0; mf < 2; ++mf) {
#pragma unroll
        for (int nf = 0; nf < 4; ++nf) {
            const int col = n0 + nw + nf * 8 + lc;
#pragma unroll
            for (int p = 0; p < 2; ++p) {
                const int row = m0 + mw + mf * 16 + lr + p * 8;
                BF2 H, L;
                split2(acc[mf][nf][2 * p + 0], H.h[0], L.h[0]);
                split2(acc[mf][nf][2 * p + 1], H.h[1], L.h[1]);
                __nv_bfloat16* o = Qw2 + (size_t)row * KS + col;
                *(uint32_t*)(o)       = H.u;
                *(uint32_t*)(o + 256) = L.u;
            }
        }
    }
}

// ======================= slim projection kernel (N=64) ======================
#define SLIM_STAGE 24576
#define SMEM_SLIM  (3 * SLIM_STAGE)

__device__ __forceinline__ void load_stage_slim(uint32_t sbase,
    const __nv_bfloat16* __restrict__ A, const __nv_bfloat16* __restrict__ W,
    int s, int tid)
{
    const __nv_bfloat16* Ak = A + amap(s) * 64;
    const __nv_bfloat16* Wk = W + bmap(s) * 64;
#pragma unroll
    for (int i = 0; i < 4; ++i) {
        const int idx = tid + i * 256;            // 1024 chunks: A 128 rows x 8
        const int r = idx >> 3, c = idx & 7;
        const uint32_t off = SMEM_SWIZZLE_128B((uint32_t)(r * 128 + c * 16));
        cp_async16(sbase + off, Ak + (size_t)r * KS + c * 8);
    }
#pragma unroll
    for (int i = 0; i < 2; ++i) {
        const int idx = tid + i * 256;            // 512 chunks: W 64 rows x 8
        const int r = idx >> 3, c = idx & 7;
        const uint32_t off = SMEM_SWIZZLE_128B((uint32_t)(r * 128 + c * 16));
        cp_async16(sbase + 16384 + off, Wk + (size_t)r * KS + c * 8);
    }
}

__global__ void __launch_bounds__(256, 3) proj_slim_kernel(
    const __nv_bfloat16* __restrict__ Q2, const __nv_bfloat16* __restrict__ K2,
    const __nv_bfloat16* __restrict__ Wp2t,
    float* __restrict__ accQ, float* __restrict__ accK,
    __nv_bfloat16* __restrict__ qph, __nv_bfloat16* __restrict__ qpl,
    __nv_bfloat16* __restrict__ kph, __nv_bfloat16* __restrict__ kpl)
{
    extern __shared__ char smem[];
    const uint32_t sb = smem_to_u32(smem);
    const int tid = threadIdx.x, wid = tid >> 5, lane = tid & 31;
    const int side = blockIdx.y;
    const int m0 = blockIdx.x * 128;
    const __nv_bfloat16* A = (side ? K2 : Q2) + (size_t)m0 * KS;
    const __nv_bfloat16* W = Wp2t + (size_t)side * 64 * KS;
    float* pf = side ? accK : accQ;
    __nv_bfloat16* ph = side ? kph : qph;
    __nv_bfloat16* pl = side ? kpl : qpl;

    const int mw = (wid >> 1) * 32, nw = (wid & 1) * 32;

    float acc[2][4][4] = {};
    load_stage_slim(sb + 0 * SLIM_STAGE, A, W, 0, tid); CP_COMMIT;
    load_stage_slim(sb + 1 * SLIM_STAGE, A, W, 1, tid); CP_COMMIT;

    for (int s = 0; s < NSTAGE; ++s) {
        CP_WAIT(1);
        __syncthreads();
        if (s + 2 < NSTAGE)
            load_stage_slim(sb + ((s + 2) % 3) * SLIM_STAGE, A, W, s + 2, tid);
        CP_COMMIT;

        const uint32_t sA = sb + (s % 3) * SLIM_STAGE;
        const uint32_t sW = sA + 16384;
#pragma unroll
        for (int kk = 0; kk < 64; kk += 16) {
            uint32_t a[2][4], b[4][2];
#pragma unroll
            for (int mf = 0; mf < 2; ++mf) {
                const uint32_t off = SMEM_SWIZZLE_128B((uint32_t)(
                    (mw + mf * 16 + (lane & 15)) * 128 + kk * 2 + ((lane >> 4) << 4)));
                ldmatrix_x4(a[mf][0], a[mf][1], a[mf][2], a[mf][3], sA + off);
            }
#pragma unroll
            for (int nb = 0; nb < 2; ++nb) {
                const int row = nw + nb * 16 + ((lane >> 4) & 1) * 8 + (lane & 7);
                const int kof = kk * 2 + (((lane >> 3) & 1) << 4);
                const uint32_t off = SMEM_SWIZZLE_128B((uint32_t)(row * 128 + kof));
                ldmatrix_x4(b[nb * 2][0], b[nb * 2][1], b[nb * 2 + 1][0], b[nb * 2 + 1][1],
                            sW + off);
            }
#pragma unroll
            for (int mf = 0; mf < 2; ++mf)
#pragma unroll
                for (int nf = 0; nf < 4; ++nf)
                    mma_bf16(acc[mf][nf], a[mf][0], a[mf][1], a[mf][2], a[mf][3],
                             b[nf][0], b[nf][1]);
        }
    }

    const int lr = lane >> 2, lc = (lane & 3) * 2;
#pragma unroll
    for (int mf = 0; mf < 2; ++mf) {
#pragma unroll
        for (int nf = 0; nf < 4; ++nf) {
            const int col = nw + nf * 8 + lc;
#pragma unroll
            for (int p = 0; p < 2; ++p) {
                const int row = m0 + mw + mf * 16 + lr + p * 8;
                const float v0 = acc[mf][nf][2 * p + 0];
                const float v1 = acc[mf][nf][2 * p + 1];
                *(float2*)(pf + (size_t)row * AN + col) = make_float2(v0, v1);
                BF2 H, L;
                split2(v0, H.h[0], L.h[0]);
                split2(v1, H.h[1], L.h[1]);
                *(uint32_t*)(ph + (size_t)row * AN + col) = H.u;
                *(uint32_t*)(pl + (size_t)row * AN + col) = L.u;
            }
        }
    }
}

// ======================= split / prep kernels =======================
__global__ void __launch_bounds__(256) split_kernel(
    const float* __restrict__ Q, const float* __restrict__ Kmat,
    __nv_bfloat16* __restrict__ Q2, __nv_bfloat16* __restrict__ K2)
{
    const int sel = blockIdx.y;
    const float* src = sel ? Kmat : Q;
    __nv_bfloat16* dst = sel ? K2 : Q2;
    const size_t i8 = (size_t)blockIdx.x * 256 + threadIdx.x;   // per 8 elems
    const size_t row = i8 >> 5;
    const int c = (int)(i8 & 31) * 8;
    const float4 v0 = ((const float4*)src)[i8 * 2];
    const float4 v1 = ((const float4*)src)[i8 * 2 + 1];
    union { __nv_bfloat16 b[8]; uint4 u; } h, l;
    split2(v0.x, h.b[0], l.b[0]); split2(v0.y, h.b[1], l.b[1]);
    split2(v0.z, h.b[2], l.b[2]); split2(v0.w, h.b[3], l.b[3]);
    split2(v1.x, h.b[4], l.b[4]); split2(v1.y, h.b[5], l.b[5]);
    split2(v1.z, h.b[6], l.b[6]); split2(v1.w, h.b[7], l.b[7]);
    __nv_bfloat16* o = dst + row * KS + c;
    *(uint4*)(o)       = h.u;
    *(uint4*)(o + 256) = l.u;
}

__global__ void __launch_bounds__(256) prep_w2t(
    const float* __restrict__ Wrel, __nv_bfloat16* __restrict__ W2t)
{
    const int idx = blockIdx.x * 256 + threadIdx.x;   // 65536
    const int d = idx >> 8, n = idx & 255;
    __nv_bfloat16 hi, lo;
    split2(Wrel[d * 256 + n], hi, lo);
    W2t[(size_t)n * KS + d]       = hi;
    W2t[(size_t)n * KS + 256 + d] = lo;
}

__global__ void __launch_bounds__(256) prep_wp(
    const float* __restrict__ Wq, const float* __restrict__ Wk,
    __nv_bfloat16* __restrict__ Wp2t)
{
    const int idx = blockIdx.x * 256 + threadIdx.x;   // 32768
    const int side = idx >> 14;
    const int d = (idx >> 6) & 255, a = idx & 63;
    const float* W = side ? Wk : Wq;
    __nv_bfloat16 hi, lo;
    split2(W[d * 64 + a], hi, lo);
    __nv_bfloat16* slab = Wp2t + (size_t)side * 64 * KS;
    slab[(size_t)a * KS + d]       = hi;
    slab[(size_t)a * KS + 256 + d] = lo;
}

// ======================= tanh + dot reduce (reads accumulators) =============
__global__ void __launch_bounds__(256) att_reduce_kernel(
    const float* __restrict__ accQ, const float* __restrict__ accK,
    const float* __restrict__ Wqa, const float* __restrict__ Wka,
    float* __restrict__ lq, float* __restrict__ lk)
{
    const int side = blockIdx.y;
    const int wid = threadIdx.x >> 5, lane = threadIdx.x & 31;
    const size_t gm = (size_t)blockIdx.x * 8 + wid;   // b*LN + m
    const float* acc = side ? accK : accQ;
    const float* w   = side ? Wka  : Wqa;
    float* out       = side ? lk   : lq;

    float s = 0.f;
#pragma unroll
    for (int h = 0; h < 2; ++h) {
        const int a = lane + h * 32;
        s += tanhf(acc[gm * AN + a]) * w[a];
    }
#pragma unroll
    for (int o = 16; o; o >>= 1) s += __shfl_xor_sync(0xFFFFFFFFu, s, o);
    if (lane == 0) out[gm] = s;
}

// ============================================================================
__global__ void __launch_bounds__(512) softmax_kernel(
    const float* __restrict__ lq, const float* __restrict__ lk,
    float* __restrict__ out)
{
    __shared__ float red[512];
    const int b = blockIdx.x, sel = blockIdx.y, t = threadIdx.x;
    const float* l = (sel ? lk : lq) + (size_t)b * LN;
    float* o = out + (sel ? OFF_KW : OFF_QW) + (size_t)b * LN;

    float v = l[t];
    red[t] = v; __syncthreads();
    for (int s = 256; s > 0; s >>= 1) {
        if (t < s) red[t] = fmaxf(red[t], red[t + s]);
        __syncthreads();
    }
    const float mx = red[0];
    __syncthreads();
    const float e = expf(v - mx);
    red[t] = e; __syncthreads();
    for (int s = 256; s > 0; s >>= 1) {
        if (t < s) red[t] += red[t + s];
        __syncthreads();
    }
    o[t] = e / red[0];
}

// weighted outputs from compact bf16 [hi|lo]: q = hi + lo
__global__ void __launch_bounds__(256) scale_kernel(
    const __nv_bfloat16* __restrict__ Q2, const __nv_bfloat16* __restrict__ K2,
    float* __restrict__ out)
{
    const int sel = blockIdx.y;
    const size_t i4 = (size_t)blockIdx.x * 256 + threadIdx.x;
    const __nv_bfloat16* src = sel ? K2 : Q2;
    const float* w = out + (sel ? OFF_KW : OFF_QW);
    float4* dst = (float4*)(out + (sel ? OFF_WK : OFF_WQ));

    const size_t e = i4 * 4;
    const size_t row = e >> 8;            // b*LN + l
    const int c = (int)(e & 255);
    const float s = w[row];

    const __nv_bfloat16* p = src + row * KS + c;
    union { __nv_bfloat16 b[4]; uint2 u; } h, l;
    h.u = *(const uint2*)(p);
    l.u = *(const uint2*)(p + 256);
    float4 v;
    v.x = (__bfloat162float(h.b[0]) + __bfloat162float(l.b[0])) * s;
    v.y = (__bfloat162float(h.b[1]) + __bfloat162float(l.b[1])) * s;
    v.z = (__bfloat162float(h.b[2]) + __bfloat162float(l.b[2])) * s;
    v.w = (__bfloat162float(h.b[3]) + __bfloat162float(l.b[3])) * s;
    dst[i4] = v;
}

// ============================================================================
extern "C" void kernel_launch(void* const* d_in, const int* in_sizes, int n_in,
                              void* d_out, int out_size)
{
    (void)in_sizes; (void)n_in; (void)out_size;
    const float* Q    = (const float*)d_in[0];
    const float* Km   = (const float*)d_in[1];
    const float* Wrel = (const float*)d_in[2];
    const float* Wq   = (const float*)d_in[3];
    const float* Wk   = (const float*)d_in[4];
    const float* Wqa  = (const float*)d_in[5];
    const float* Wka  = (const float*)d_in[6];
    float* out = (float*)d_out;

    __nv_bfloat16 *q2, *k2, *qw2, *w2t, *wp2t, *qph, *qpl, *kph, *kpl;
    float *aQ, *aK, *lq, *lk;
    cudaGetSymbolAddress((void**)&q2,   g_Q2);
    cudaGetSymbolAddress((void**)&k2,   g_K2);
    cudaGetSymbolAddress((void**)&qw2,  g_Qw2);
    cudaGetSymbolAddress((void**)&w2t,  g_W2t);
    cudaGetSymbolAddress((void**)&wp2t, g_Wp2t);
    cudaGetSymbolAddress((void**)&aQ,   g_accQ);
    cudaGetSymbolAddress((void**)&aK,   g_accK);
    cudaGetSymbolAddress((void**)&qph,  g_qph);
    cudaGetSymbolAddress((void**)&qpl,  g_qpl);
    cudaGetSymbolAddress((void**)&kph,  g_kph);
    cudaGetSymbolAddress((void**)&kpl,  g_kpl);
    cudaGetSymbolAddress((void**)&lq,   g_logit_q);
    cudaGetSymbolAddress((void**)&lk,   g_logit_k);

    cudaFuncSetAttribute(qw_slim_kernel,   cudaFuncAttributeMaxDynamicSharedMemorySize, SMEM_QWS);
    cudaFuncSetAttribute(proj_slim_kernel, cudaFuncAttributeMaxDynamicSharedMemorySize, SMEM_SLIM);
    cudaFuncSetAttribute(rel_fused_kernel, cudaFuncAttributeMaxDynamicSharedMemorySize, SMEM_FUSED);

    const dim3 blk(256);
    // compact [hi|lo] splits of inputs + weight transposes
    split_kernel<<<dim3((BN * LN * DN) / 8 / 256, 2), blk>>>(Q, Km, q2, k2);
    prep_w2t<<<256, blk>>>(Wrel, w2t);
    prep_wp<<<128, blk>>>(Wq, Wk, wp2t);
    // projections -> accumulator base values + bf16 hi/lo copies
    proj_slim_kernel<<<dim3(512, 2), blk, SMEM_SLIM>>>(
        q2, k2, wp2t, aQ, aK, qph, qpl, kph, kpl);
    // Qw (slim 64x128 tiles, 3 CTA/SM; n fastest for Q2 L2 reuse)
    qw_slim_kernel<<<dim3(2, 1024), blk, SMEM_QWS>>>(q2, w2t, qw2);
    // fused rel (chunk-set mainloop) + both score GEMMs -> REDs into accumulators
    rel_fused_kernel<<<dim3(4, 4, BN), blk, SMEM_FUSED>>>(qw2, k2, kph, kpl, qph, qpl, aQ, aK);
    // tanh + @W_att -> logits
    att_reduce_kernel<<<dim3(BN * LN / 8, 2), blk>>>(aQ, aK, Wqa, Wka, lq, lk);
    // softmax -> weights in d_out
    softmax_kernel<<<dim3(BN, 2), 512>>>(lq, lk, out);
    // weighted outputs from compact bf16
    scale_kernel<<<dim3((BN * LN * DN) / 4 / 256, 2), 256>>>(q2, k2, out);
}

// round 16
// speedup vs baseline: 1.0706x; 1.0274x over previous
#include <cuda_runtime.h>
#include <cuda_bf16.h>
#include <math.h>
#include <stdint.h>

// Problem dims
#define BN 128
#define LN 512
#define DN 256
#define AN 64
#define KS 512   // compact split storage: [hi | lo] x 256

// Output layout (concatenated, reference tuple order)
#define OFF_WQ  ((size_t)0)
#define OFF_WK  ((size_t)BN * LN * DN)
#define OFF_QW  ((size_t)2 * BN * LN * DN)
#define OFF_KW  (OFF_QW + (size_t)BN * LN)

// -------- scratch (device globals; no allocation allowed) --------
__device__ __nv_bfloat16 g_Q2 [(size_t)BN * LN * KS];    // [hi|lo] of Q
__device__ __nv_bfloat16 g_K2 [(size_t)BN * LN * KS];    // [hi|lo] of K
__device__ __nv_bfloat16 g_Qw2[(size_t)BN * LN * KS];    // [hi|lo] of Qw
__device__ __nv_bfloat16 g_W2t[(size_t)DN * KS];         // W_rel^T [hi|lo]
__device__ __nv_bfloat16 g_Wp2t[2 * 64 * KS];            // Wq^T / Wk^T [hi|lo]
__device__ float g_accQ[(size_t)BN * LN * AN];           // q_proj + rel@kp
__device__ float g_accK[(size_t)BN * LN * AN];           // k_proj + relT@qp
__device__ __nv_bfloat16 g_qph[(size_t)BN * LN * AN], g_qpl[(size_t)BN * LN * AN];
__device__ __nv_bfloat16 g_kph[(size_t)BN * LN * AN], g_kpl[(size_t)BN * LN * AN];

// ======================= helpers (baseline PTX only) =======================
__device__ __forceinline__ uint32_t smem_to_u32(const void* p) {
    uint32_t a;
    asm("{ .reg .u64 t; cvta.to.shared.u64 t, %1; cvt.u32.u64 %0, t; }" : "=r"(a) : "l"(p));
    return a;
}
#define SMEM_SWIZZLE_128B(o) ((o) ^ (((o) >> 3) & 0x70))

__device__ __forceinline__ void cp_async16(uint32_t saddr, const void* g) {
    asm volatile("cp.async.cg.shared.global [%0], [%1], 16;" :: "r"(saddr), "l"(g));
}
#define CP_COMMIT  asm volatile("cp.async.commit_group;" ::: "memory")
#define CP_WAIT(n) asm volatile("cp.async.wait_group %0;" :: "n"(n) : "memory")

__device__ __forceinline__ void ldmatrix_x4(uint32_t& r0, uint32_t& r1, uint32_t& r2,
                                            uint32_t& r3, uint32_t addr) {
    asm volatile("ldmatrix.sync.aligned.m8n8.x4.shared.b16 {%0,%1,%2,%3}, [%4];"
                 : "=r"(r0), "=r"(r1), "=r"(r2), "=r"(r3) : "r"(addr));
}
__device__ __forceinline__ void ldmatrix_x4_trans(uint32_t& r0, uint32_t& r1, uint32_t& r2,
                                                  uint32_t& r3, uint32_t addr) {
    asm volatile("ldmatrix.sync.aligned.m8n8.x4.trans.shared.b16 {%0,%1,%2,%3}, [%4];"
                 : "=r"(r0), "=r"(r1), "=r"(r2), "=r"(r3) : "r"(addr));
}
__device__ __forceinline__ void mma_bf16(float* c, uint32_t a0, uint32_t a1, uint32_t a2,
                                         uint32_t a3, uint32_t b0, uint32_t b1) {
    asm volatile(
        "mma.sync.aligned.m16n8k16.row.col.f32.bf16.bf16.f32 "
        "{%0,%1,%2,%3}, {%4,%5,%6,%7}, {%8,%9}, {%0,%1,%2,%3};"
        : "+f"(c[0]), "+f"(c[1]), "+f"(c[2]), "+f"(c[3])
        : "r"(a0), "r"(a1), "r"(a2), "r"(a3), "r"(b0), "r"(b1));
}
__device__ __forceinline__ void red_add_v2(float* addr, float a, float b) {
    asm volatile("red.global.add.v2.f32 [%0], {%1, %2};"
                 :: "l"(addr), "f"(a), "f"(b) : "memory");
}

__device__ __forceinline__ void split2(float x, __nv_bfloat16& hi, __nv_bfloat16& lo) {
    hi = __float2bfloat16(x);
    lo = __float2bfloat16(x - __bfloat162float(hi));
}
union BF2 { __nv_bfloat16 h[2]; uint32_t u; };

// fast tanh: exact to ~1e-7 abs (MUFU-based __expf + fast div), branch-free
__device__ __forceinline__ float tanh_fast(float x) {
    const float e = __expf(-2.f * fabsf(x));
    const float r = __fdividef(1.f - e, 1.f + e);
    return copysignf(r, x);
}

// Stage maps for the 12-stage kernels (qw/proj): s 0-3 hi*hi, 4-7 lo*hi, 8-11 hi*lo.
__device__ __forceinline__ int amap(int s) { return s < 8 ? s : s - 8; }
__device__ __forceinline__ int bmap(int s) { return s < 4 ? s : s - 4; }

#define NSTAGE  12
#define STAGE_BYTES 32768

// ======================= fused rel + att-score kernel =======================
#define R_PITCH  272          // 128 cols bf16 (256B) + 16B pad
#define P_PITCH  144          // 64 cols bf16 (128B) + 16B pad
#define RH_OFF   0
#define RL_OFF   34816
#define PJH_OFF  69632
#define PJL_OFF  88064
#define SMEM_FUSED 106496     // >= 3*STAGE_BYTES mainloop ring

__device__ __forceinline__ void load_half_rel(uint32_t sbase,
    const __nv_bfloat16* __restrict__ A, const __nv_bfloat16* __restrict__ B,
    int h, int tid)
{
    const int koff = (h & 1) * 256 + (h >> 1) * 64;   // hi/lo part + chunk
    const __nv_bfloat16* Ak = A + koff;
    const __nv_bfloat16* Bk = B + koff;
#pragma unroll
    for (int i = 0; i < 4; ++i) {
        const int idx = tid + i * 256;            // 0..1023 16B chunks
        const int r = idx >> 3, c = idx & 7;
        const uint32_t off = SMEM_SWIZZLE_128B((uint32_t)(r * 128 + c * 16));
        cp_async16(sbase + off, Ak + (size_t)r * KS + c * 8);
        cp_async16(sbase + 16384 + off, Bk + (size_t)r * KS + c * 8);
    }
}

__global__ void __launch_bounds__(256, 2) rel_fused_kernel(
    const __nv_bfloat16* __restrict__ Qw2, const __nv_bfloat16* __restrict__ K2,
    const __nv_bfloat16* __restrict__ kph, const __nv_bfloat16* __restrict__ kpl,
    const __nv_bfloat16* __restrict__ qph, const __nv_bfloat16* __restrict__ qpl,
    float* __restrict__ accQ, float* __restrict__ accK)
{
    extern __shared__ char smem[];
    const uint32_t sb = smem_to_u32(smem);
    const int tid = threadIdx.x, wid = tid >> 5, lane = tid & 31;
    const int mt = blockIdx.x, nt = blockIdx.y, b = blockIdx.z;
    const int m0 = mt * 128, n0 = nt * 128;
    const int mw = (wid >> 2) * 64, nw = (wid & 3) * 32;

    float acc[4][4][4] = {};
    {
        const __nv_bfloat16* A = Qw2 + ((size_t)b * LN + m0) * KS;
        const __nv_bfloat16* B = K2  + ((size_t)b * LN + n0) * KS;

        load_half_rel(sb + 0 * STAGE_BYTES, A, B, 0, tid); CP_COMMIT;
        load_half_rel(sb + 1 * STAGE_BYTES, A, B, 1, tid); CP_COMMIT;

        int sa = 0;   // ring slot of half 2c (hi)
        for (int c = 0; c < 4; ++c) {
            const int sl = (sa + 1 == 3) ? 0 : sa + 1;   // slot of half 2c+1 (lo)
            const int sp = (sl + 1 == 3) ? 0 : sl + 1;   // slot for half 2c+2
            if (c < 3) load_half_rel(sb + sp * STAGE_BYTES, A, B, 2 * c + 2, tid);
            CP_COMMIT;
            CP_WAIT(1);            // halves 2c, 2c+1 complete
            __syncthreads();

            const uint32_t bAh = sb + sa * STAGE_BYTES;
            const uint32_t bAl = sb + sl * STAGE_BYTES;
#pragma unroll
            for (int kk = 0; kk < 64; kk += 16) {
                uint32_t aH[4][4], bb[4][2];
#pragma unroll
                for (int mf = 0; mf < 4; ++mf) {
                    const uint32_t off = SMEM_SWIZZLE_128B((uint32_t)(
                        (mw + mf * 16 + (lane & 15)) * 128 + kk * 2 + ((lane >> 4) << 4)));
                    ldmatrix_x4(aH[mf][0], aH[mf][1], aH[mf][2], aH[mf][3], bAh + off);
                }
#pragma unroll
                for (int nb = 0; nb < 2; ++nb) {
                    const int row = nw + nb * 16 + ((lane >> 4) & 1) * 8 + (lane & 7);
                    const int kof = kk * 2 + (((lane >> 3) & 1) << 4);
                    const uint32_t off = SMEM_SWIZZLE_128B((uint32_t)(row * 128 + kof));
                    ldmatrix_x4(bb[nb * 2][0], bb[nb * 2][1], bb[nb * 2 + 1][0],
                                bb[nb * 2 + 1][1], bAh + 16384 + off);
                }
                // hh
#pragma unroll
                for (int mf = 0; mf < 4; ++mf)
#pragma unroll
                    for (int nf = 0; nf < 4; ++nf)
                        mma_bf16(acc[mf][nf], aH[mf][0], aH[mf][1], aH[mf][2], aH[mf][3],
                                 bb[nf][0], bb[nf][1]);
                // lh (aL scoped to bound register peak)
                {
                    uint32_t aL[4][4];
#pragma unroll
                    for (int mf = 0; mf < 4; ++mf) {
                        const uint32_t off = SMEM_SWIZZLE_128B((uint32_t)(
                            (mw + mf * 16 + (lane & 15)) * 128 + kk * 2 + ((lane >> 4) << 4)));
                        ldmatrix_x4(aL[mf][0], aL[mf][1], aL[mf][2], aL[mf][3], bAl + off);
                    }
#pragma unroll
                    for (int mf = 0; mf < 4; ++mf)
#pragma unroll
                        for (int nf = 0; nf < 4; ++nf)
                            mma_bf16(acc[mf][nf], aL[mf][0], aL[mf][1], aL[mf][2], aL[mf][3],
                                     bb[nf][0], bb[nf][1]);
                }
                // hl (reuse bb registers for B-lo)
#pragma unroll
                for (int nb = 0; nb < 2; ++nb) {
                    const int row = nw + nb * 16 + ((lane >> 4) & 1) * 8 + (lane & 7);
                    const int kof = kk * 2 + (((lane >> 3) & 1) << 4);
                    const uint32_t off = SMEM_SWIZZLE_128B((uint32_t)(row * 128 + kof));
                    ldmatrix_x4(bb[nb * 2][0], bb[nb * 2][1], bb[nb * 2 + 1][0],
                                bb[nb * 2 + 1][1], bAl + 16384 + off);
                }
#pragma unroll
                for (int mf = 0; mf < 4; ++mf)
#pragma unroll
                    for (int nf = 0; nf < 4; ++nf)
                        mma_bf16(acc[mf][nf], aH[mf][0], aH[mf][1], aH[mf][2], aH[mf][3],
                                 bb[nf][0], bb[nf][1]);
            }
            __syncthreads();   // ring slots free before reuse / before rel smem stores
            if (c < 3) { load_half_rel(sb + sa * STAGE_BYTES, A, B, 2 * c + 3, tid); CP_COMMIT; }
            sa = sp;
        }
    }

    // prefetch kp hi/lo tiles (rows n0..n0+127) while storing rel to smem
    {
        const __nv_bfloat16* kh = kph + ((size_t)b * LN + n0) * AN;
        const __nv_bfloat16* kl = kpl + ((size_t)b * LN + n0) * AN;
#pragma unroll
        for (int i = 0; i < 4; ++i) {
            const int idx = tid + i * 256, r = idx >> 3, c = idx & 7;
            cp_async16(sb + PJH_OFF + r * P_PITCH + c * 16, kh + (size_t)r * AN + c * 8);
            cp_async16(sb + PJL_OFF + r * P_PITCH + c * 16, kl + (size_t)r * AN + c * 8);
        }
        CP_COMMIT;
    }

    // fast tanh + hi/lo split -> smem rel tiles
    const int lr = lane >> 2, lc = (lane & 3) * 2;
#pragma unroll
    for (int mf = 0; mf < 4; ++mf)
#pragma unroll
        for (int nf = 0; nf < 4; ++nf)
#pragma unroll
            for (int p = 0; p < 2; ++p) {
                const int rr = mw + mf * 16 + lr + p * 8;
                const int cc = nw + nf * 8 + lc;
                BF2 H, L;
                split2(tanh_fast(acc[mf][nf][2 * p + 0]), H.h[0], L.h[0]);
                split2(tanh_fast(acc[mf][nf][2 * p + 1]), H.h[1], L.h[1]);
                *(uint32_t*)(smem + RH_OFF + rr * R_PITCH + cc * 2) = H.u;
                *(uint32_t*)(smem + RL_OFF + rr * R_PITCH + cc * 2) = L.u;
            }
    CP_WAIT(0);
    __syncthreads();

    // ---- C2[m][a] = sum_n rel[m][n] * kp[n0+n][a]
    float c2[8][4] = {};
#pragma unroll
    for (int kk = 0; kk < 128; kk += 16) {
        uint32_t aH0, aH1, aH2, aH3, aL0, aL1, aL2, aL3;
        const uint32_t aoff = (16 * wid + (lane & 15)) * R_PITCH
                            + (kk + ((lane >> 4) << 3)) * 2;
        ldmatrix_x4(aH0, aH1, aH2, aH3, sb + RH_OFF + aoff);
        ldmatrix_x4(aL0, aL1, aL2, aL3, sb + RL_OFF + aoff);
#pragma unroll
        for (int ab = 0; ab < 4; ++ab) {
            uint32_t h0, h1, h2, h3, l0, l1, l2, l3;
            const uint32_t boff = (kk + (lane & 15)) * P_PITCH
                                + (ab * 16 + ((lane >> 4) << 3)) * 2;
            ldmatrix_x4_trans(h0, h1, h2, h3, sb + PJH_OFF + boff);
            ldmatrix_x4_trans(l0, l1, l2, l3, sb + PJL_OFF + boff);
            mma_bf16(c2[2 * ab],     aH0, aH1, aH2, aH3, h0, h1);
            mma_bf16(c2[2 * ab],     aL0, aL1, aL2, aL3, h0, h1);
            mma_bf16(c2[2 * ab],     aH0, aH1, aH2, aH3, l0, l1);
            mma_bf16(c2[2 * ab + 1], aH0, aH1, aH2, aH3, h2, h3);
            mma_bf16(c2[2 * ab + 1], aL0, aL1, aL2, aL3, h2, h3);
            mma_bf16(c2[2 * ab + 1], aH0, aH1, aH2, aH3, l2, l3);
        }
    }
    {
        float* base = accQ + ((size_t)b * LN + m0 + 16 * wid) * AN;
#pragma unroll
        for (int j = 0; j < 8; ++j) {
            const int col = j * 8 + lc;
            red_add_v2(base + (size_t)lr * AN + col,       c2[j][0], c2[j][1]);
            red_add_v2(base + (size_t)(lr + 8) * AN + col, c2[j][2], c2[j][3]);
        }
    }
    __syncthreads();   // all warps done reading kp tiles

    // load qp hi/lo tiles (rows m0..m0+127) into same region
    {
        const __nv_bfloat16* qh = qph + ((size_t)b * LN + m0) * AN;
        const __nv_bfloat16* ql = qpl + ((size_t)b * LN + m0) * AN;
#pragma unroll
        for (int i = 0; i < 4; ++i) {
            const int idx = tid + i * 256, r = idx >> 3, c = idx & 7;
            cp_async16(sb + PJH_OFF + r * P_PITCH + c * 16, qh + (size_t)r * AN + c * 8);
            cp_async16(sb + PJL_OFF + r * P_PITCH + c * 16, ql + (size_t)r * AN + c * 8);
        }
        CP_COMMIT; CP_WAIT(0);
    }
    __syncthreads();

    // ---- C3[n][a] = sum_m rel[m][n] * qp[m0+m][a]  (A = rel^T via ldmatrix.trans)
    float c3[8][4] = {};
    const int g = lane >> 3;
#pragma unroll
    for (int kk = 0; kk < 128; kk += 16) {
        uint32_t aH0, aH1, aH2, aH3, aL0, aL1, aL2, aL3;
        const uint32_t aoff = (kk + ((g >> 1) << 3) + (lane & 7)) * R_PITCH
                            + (16 * wid + ((g & 1) << 3)) * 2;
        ldmatrix_x4_trans(aH0, aH1, aH2, aH3, sb + RH_OFF + aoff);
        ldmatrix_x4_trans(aL0, aL1, aL2, aL3, sb + RL_OFF + aoff);
#pragma unroll
        for (int ab = 0; ab < 4; ++ab) {
            uint32_t h0, h1, h2, h3, l0, l1, l2, l3;
            const uint32_t boff = (kk + (lane & 15)) * P_PITCH
                                + (ab * 16 + ((lane >> 4) << 3)) * 2;
            ldmatrix_x4_trans(h0, h1, h2, h3, sb + PJH_OFF + boff);
            ldmatrix_x4_trans(l0, l1, l2, l3, sb + PJL_OFF + boff);
            mma_bf16(c3[2 * ab],     aH0, aH1, aH2, aH3, h0, h1);
            mma_bf16(c3[2 * ab],     aL0, aL1, aL2, aL3, h0, h1);
            mma_bf16(c3[2 * ab],     aH0, aH1, aH2, aH3, l0, l1);
            mma_bf16(c3[2 * ab + 1], aH0, aH1, aH2, aH3, h2, h3);
            mma_bf16(c3[2 * ab + 1], aL0, aL1, aL2, aL3, h2, h3);
            mma_bf16(c3[2 * ab + 1], aH0, aH1, aH2, aH3, l2, l3);
        }
    }
    {
        float* base = accK + ((size_t)b * LN + n0 + 16 * wid) * AN;
#pragma unroll
        for (int j = 0; j < 8; ++j) {
            const int col = j * 8 + lc;
            red_add_v2(base + (size_t)lr * AN + col,       c3[j][0], c3[j][1]);
            red_add_v2(base + (size_t)(lr + 8) * AN + col, c3[j][2], c3[j][3]);
        }
    }
}

// ======================= slim Qw kernel (CTA 64m x 128n, 3 CTA/SM) ==========
#define QWS_STAGE 24576
#define SMEM_QWS  (3 * QWS_STAGE)

__device__ __forceinline__ void load_stage_qws(uint32_t sbase,
    const __nv_bfloat16* __restrict__ A, const __nv_bfloat16* __restrict__ B,
    int s, int tid)
{
    const __nv_bfloat16* Ak = A + amap(s) * 64;
    const __nv_bfloat16* Bk = B + bmap(s) * 64;
#pragma unroll
    for (int i = 0; i < 2; ++i) {
        const int idx = tid + i * 256;            // 512 chunks: A 64 rows x 8
        const int r = idx >> 3, c = idx & 7;
        const uint32_t off = SMEM_SWIZZLE_128B((uint32_t)(r * 128 + c * 16));
        cp_async16(sbase + off, Ak + (size_t)r * KS + c * 8);
    }
#pragma unroll
    for (int i = 0; i < 4; ++i) {
        const int idx = tid + i * 256;            // 1024 chunks: B 128 rows x 8
        const int r = idx >> 3, c = idx & 7;
        const uint32_t off = SMEM_SWIZZLE_128B((uint32_t)(r * 128 + c * 16));
        cp_async16(sbase + 8192 + off, Bk + (size_t)r * KS + c * 8);
    }
}

__global__ void __launch_bounds__(256, 3) qw_slim_kernel(
    const __nv_bfloat16* __restrict__ Q2, const __nv_bfloat16* __restrict__ W2t,
    __nv_bfloat16* __restrict__ Qw2)
{
    extern __shared__ char smem[];
    const uint32_t sb = smem_to_u32(smem);
    const int tid = threadIdx.x, wid = tid >> 5, lane = tid & 31;
    const int m0 = blockIdx.y * 64, n0 = blockIdx.x * 128;   // n fastest
    const __nv_bfloat16* A = Q2  + (size_t)m0 * KS;
    const __nv_bfloat16* B = W2t + (size_t)n0 * KS;

    const int mw = (wid >> 2) * 32, nw = (wid & 3) * 32;

    float acc[2][4][4] = {};
    load_stage_qws(sb + 0 * QWS_STAGE, A, B, 0, tid); CP_COMMIT;
    load_stage_qws(sb + 1 * QWS_STAGE, A, B, 1, tid); CP_COMMIT;

    for (int s = 0; s < NSTAGE; ++s) {
        CP_WAIT(1);
        __syncthreads();
        if (s + 2 < NSTAGE)
            load_stage_qws(sb + ((s + 2) % 3) * QWS_STAGE, A, B, s + 2, tid);
        CP_COMMIT;

        const uint32_t sA = sb + (s % 3) * QWS_STAGE;
        const uint32_t sB = sA + 8192;
#pragma unroll
        for (int kk = 0; kk < 64; kk += 16) {
            uint32_t a[2][4], b[4][2];
#pragma unroll
            for (int mf = 0; mf < 2; ++mf) {
                const uint32_t off = SMEM_SWIZZLE_128B((uint32_t)(
                    (mw + mf * 16 + (lane & 15)) * 128 + kk * 2 + ((lane >> 4) << 4)));
                ldmatrix_x4(a[mf][0], a[mf][1], a[mf][2], a[mf][3], sA + off);
            }
#pragma unroll
            for (int nb = 0; nb < 2; ++nb) {
                const int row = nw + nb * 16 + ((lane >> 4) & 1) * 8 + (lane & 7);
                const int kof = kk * 2 + (((lane >> 3) & 1) << 4);
                const uint32_t off = SMEM_SWIZZLE_128B((uint32_t)(row * 128 + kof));
                ldmatrix_x4(b[nb * 2][0], b[nb * 2][1], b[nb * 2 + 1][0], b[nb * 2 + 1][1],
                            sB + off);
            }
#pragma unroll
            for (int mf = 0; mf < 2; ++mf)
#pragma unroll
                for (int nf = 0; nf < 4; ++nf)
                    mma_bf16(acc[mf][nf], a[mf][0], a[mf][1], a[mf][2], a[mf][3],
                             b[nf][0], b[nf][1]);
        }
    }

    const int lr = lane >> 2, lc = (lane & 3) * 2;
#pragma unroll
    for (int mf = 0; mf < 2; ++mf) {
#pragma unroll
        for (int nf = 0; nf < 4; ++nf) {
            const int col = n0 + nw + nf * 8 + lc;
#pragma unroll
            for (int p = 0; p < 2; ++p) {
                const int row = m0 + mw + mf * 16 + lr + p * 8;
                BF2 H, L;
                split2(acc[mf][nf][2 * p + 0], H.h[0], L.h[0]);
                split2(acc[mf][nf][2 * p + 1], H.h[1], L.h[1]);
                __nv_bfloat16* o = Qw2 + (size_t)row * KS + col;
                *(uint32_t*)(o)       = H.u;
                *(uint32_t*)(o + 256) = L.u;
            }
        }
    }
}

// ======================= slim projection kernel (N=64) ======================
#define SLIM_STAGE 24576
#define SMEM_SLIM  (3 * SLIM_STAGE)

__device__ __forceinline__ void load_stage_slim(uint32_t sbase,
    const __nv_bfloat16* __restrict__ A, const __nv_bfloat16* __restrict__ W,
    int s, int tid)
{
    const __nv_bfloat16* Ak = A + amap(s) * 64;
    const __nv_bfloat16* Wk = W + bmap(s) * 64;
#pragma unroll
    for (int i = 0; i < 4; ++i) {
        const int idx = tid + i * 256;            // 1024 chunks: A 128 rows x 8
        const int r = idx >> 3, c = idx & 7;
        const uint32_t off = SMEM_SWIZZLE_128B((uint32_t)(r * 128 + c * 16));
        cp_async16(sbase + off, Ak + (size_t)r * KS + c * 8);
    }
#pragma unroll
    for (int i = 0; i < 2; ++i) {
        const int idx = tid + i * 256;            // 512 chunks: W 64 rows x 8
        const int r = idx >> 3, c = idx & 7;
        const uint32_t off = SMEM_SWIZZLE_128B((uint32_t)(r * 128 + c * 16));
        cp_async16(sbase + 16384 + off, Wk + (size_t)r * KS + c * 8);
    }
}

__global__ void __launch_bounds__(256, 3) proj_slim_kernel(
    const __nv_bfloat16* __restrict__ Q2, const __nv_bfloat16* __restrict__ K2,
    const __nv_bfloat16* __restrict__ Wp2t,
    float* __restrict__ accQ, float* __restrict__ accK,
    __nv_bfloat16* __restrict__ qph, __nv_bfloat16* __restrict__ qpl,
    __nv_bfloat16* __restrict__ kph, __nv_bfloat16* __restrict__ kpl)
{
    extern __shared__ char smem[];
    const uint32_t sb = smem_to_u32(smem);
    const int tid = threadIdx.x, wid = tid >> 5, lane = tid & 31;
    const int side = blockIdx.y;
    const int m0 = blockIdx.x * 128;
    const __nv_bfloat16* A = (side ? K2 : Q2) + (size_t)m0 * KS;
    const __nv_bfloat16* W = Wp2t + (size_t)side * 64 * KS;
    float* pf = side ? accK : accQ;
    __nv_bfloat16* ph = side ? kph : qph;
    __nv_bfloat16* pl = side ? kpl : qpl;

    const int mw = (wid >> 1) * 32, nw = (wid & 1) * 32;

    float acc[2][4][4] = {};
    load_stage_slim(sb + 0 * SLIM_STAGE, A, W, 0, tid); CP_COMMIT;
    load_stage_slim(sb + 1 * SLIM_STAGE, A, W, 1, tid); CP_COMMIT;

    for (int s = 0; s < NSTAGE; ++s) {
        CP_WAIT(1);
        __syncthreads();
        if (s + 2 < NSTAGE)
            load_stage_slim(sb + ((s + 2) % 3) * SLIM_STAGE, A, W, s + 2, tid);
        CP_COMMIT;

        const uint32_t sA = sb + (s % 3) * SLIM_STAGE;
        const uint32_t sW = sA + 16384;
#pragma unroll
        for (int kk = 0; kk < 64; kk += 16) {
            uint32_t a[2][4], b[4][2];
#pragma unroll
            for (int mf = 0; mf < 2; ++mf) {
                const uint32_t off = SMEM_SWIZZLE_128B((uint32_t)(
                    (mw + mf * 16 + (lane & 15)) * 128 + kk * 2 + ((lane >> 4) << 4)));
                ldmatrix_x4(a[mf][0], a[mf][1], a[mf][2], a[mf][3], sA + off);
            }
#pragma unroll
            for (int nb = 0; nb < 2; ++nb) {
                const int row = nw + nb * 16 + ((lane >> 4) & 1) * 8 + (lane & 7);
                const int kof = kk * 2 + (((lane >> 3) & 1) << 4);
                const uint32_t off = SMEM_SWIZZLE_128B((uint32_t)(row * 128 + kof));
                ldmatrix_x4(b[nb * 2][0], b[nb * 2][1], b[nb * 2 + 1][0], b[nb * 2 + 1][1],
                            sW + off);
            }
#pragma unroll
            for (int mf = 0; mf < 2; ++mf)
#pragma unroll
                for (int nf = 0; nf < 4; ++nf)
                    mma_bf16(acc[mf][nf], a[mf][0], a[mf][1], a[mf][2], a[mf][3],
                             b[nf][0], b[nf][1]);
        }
    }

    const int lr = lane >> 2, lc = (lane & 3) * 2;
#pragma unroll
    for (int mf = 0; mf < 2; ++mf) {
#pragma unroll
        for (int nf = 0; nf < 4; ++nf) {
            const int col = nw + nf * 8 + lc;
#pragma unroll
            for (int p = 0; p < 2; ++p) {
                const int row = m0 + mw + mf * 16 + lr + p * 8;
                const float v0 = acc[mf][nf][2 * p + 0];
                const float v1 = acc[mf][nf][2 * p + 1];
                *(float2*)(pf + (size_t)row * AN + col) = make_float2(v0, v1);
                BF2 H, L;
                split2(v0, H.h[0], L.h[0]);
                split2(v1, H.h[1], L.h[1]);
                *(uint32_t*)(ph + (size_t)row * AN + col) = H.u;
                *(uint32_t*)(pl + (size_t)row * AN + col) = L.u;
            }
        }
    }
}

// ======================= combined prep kernel (ONE launch) ==================
// blocks [0, 16384): input split; [16384, 16640): W_rel^T; [16640, 16768): Wq/Wk
__global__ void __launch_bounds__(256) prep_all_kernel(
    const float* __restrict__ Q, const float* __restrict__ Kmat,
    const float* __restrict__ Wrel, const float* __restrict__ Wq,
    const float* __restrict__ Wk,
    __nv_bfloat16* __restrict__ Q2, __nv_bfloat16* __restrict__ K2,
    __nv_bfloat16* __restrict__ W2t, __nv_bfloat16* __restrict__ Wp2t)
{
    const int bx = blockIdx.x;
    if (bx < 16384) {
        const int sel = bx >> 13;
        const float* src = sel ? Kmat : Q;
        __nv_bfloat16* dst = sel ? K2 : Q2;
        const size_t i8 = (size_t)(bx & 8191) * 256 + threadIdx.x;   // per 8 elems
        const size_t row = i8 >> 5;
        const int c = (int)(i8 & 31) * 8;
        const float4 v0 = ((const float4*)src)[i8 * 2];
        const float4 v1 = ((const float4*)src)[i8 * 2 + 1];
        union { __nv_bfloat16 b[8]; uint4 u; } h, l;
        split2(v0.x, h.b[0], l.b[0]); split2(v0.y, h.b[1], l.b[1]);
        split2(v0.z, h.b[2], l.b[2]); split2(v0.w, h.b[3], l.b[3]);
        split2(v1.x, h.b[4], l.b[4]); split2(v1.y, h.b[5], l.b[5]);
        split2(v1.z, h.b[6], l.b[6]); split2(v1.w, h.b[7], l.b[7]);
        __nv_bfloat16* o = dst + row * KS + c;
        *(uint4*)(o)       = h.u;
        *(uint4*)(o + 256) = l.u;
    } else if (bx < 16640) {
        const int idx = (bx - 16384) * 256 + threadIdx.x;   // 65536
        const int d = idx >> 8, n = idx & 255;
        __nv_bfloat16 hi, lo;
        split2(Wrel[d * 256 + n], hi, lo);
        W2t[(size_t)n * KS + d]       = hi;
        W2t[(size_t)n * KS + 256 + d] = lo;
    } else {
        const int idx = (bx - 16640) * 256 + threadIdx.x;   // 32768
        const int side = idx >> 14;
        const int d = (idx >> 6) & 255, a = idx & 63;
        const float* W = side ? Wk : Wq;
        __nv_bfloat16 hi, lo;
        split2(W[d * 64 + a], hi, lo);
        __nv_bfloat16* slab = Wp2t + (size_t)side * 64 * KS;
        slab[(size_t)a * KS + d]       = hi;
        slab[(size_t)a * KS + 256 + d] = lo;
    }
}

// ======================= fused tanh-dot + softmax ===========================
// block = (b, side); thread t owns row t: 64-dot -> logit -> in-block softmax
__global__ void __launch_bounds__(512) logits_kernel(
    const float* __restrict__ accQ, const float* __restrict__ accK,
    const float* __restrict__ Wqa, const float* __restrict__ Wka,
    float* __restrict__ out)
{
    __shared__ float red[512];
    __shared__ float wsh[AN];
    const int b = blockIdx.x, side = blockIdx.y, t = threadIdx.x;
    const float* acc = (side ? accK : accQ) + ((size_t)b * LN + t) * AN;
    const float* w   = side ? Wka : Wqa;
    float* o = out + (side ? OFF_KW : OFF_QW) + (size_t)b * LN;

    if (t < AN) wsh[t] = w[t];
    __syncthreads();

    float s = 0.f;
    const float4* row = (const float4*)acc;
#pragma unroll
    for (int i = 0; i < AN / 4; ++i) {
        const float4 v = row[i];
        s += tanh_fast(v.x) * wsh[4 * i]     + tanh_fast(v.y) * wsh[4 * i + 1]
           + tanh_fast(v.z) * wsh[4 * i + 2] + tanh_fast(v.w) * wsh[4 * i + 3];
    }

    red[t] = s; __syncthreads();
    for (int st = 256; st > 0; st >>= 1) {
        if (t < st) red[t] = fmaxf(red[t], red[t + st]);
        __syncthreads();
    }
    const float mx = red[0];
    __syncthreads();
    const float e = __expf(s - mx);
    red[t] = e; __syncthreads();
    for (int st = 256; st > 0; st >>= 1) {
        if (t < st) red[t] += red[t + st];
        __syncthreads();
    }
    o[t] = e / red[0];
}

// weighted outputs from compact bf16 [hi|lo]: q = hi + lo
__global__ void __launch_bounds__(256) scale_kernel(
    const __nv_bfloat16* __restrict__ Q2, const __nv_bfloat16* __restrict__ K2,
    float* __restrict__ out)
{
    const int sel = blockIdx.y;
    const size_t i4 = (size_t)blockIdx.x * 256 + threadIdx.x;
    const __nv_bfloat16* src = sel ? K2 : Q2;
    const float* w = out + (sel ? OFF_KW : OFF_QW);
    float4* dst = (float4*)(out + (sel ? OFF_WK : OFF_WQ));

    const size_t e = i4 * 4;
    const size_t row = e >> 8;            // b*LN + l
    const int c = (int)(e & 255);
    const float s = w[row];

    const __nv_bfloat16* p = src + row * KS + c;
    union { __nv_bfloat16 b[4]; uint2 u; } h, l;
    h.u = *(const uint2*)(p);
    l.u = *(const uint2*)(p + 256);
    float4 v;
    v.x = (__bfloat162float(h.b[0]) + __bfloat162float(l.b[0])) * s;
    v.y = (__bfloat162float(h.b[1]) + __bfloat162float(l.b[1])) * s;
    v.z = (__bfloat162float(h.b[2]) + __bfloat162float(l.b[2])) * s;
    v.w = (__bfloat162float(h.b[3]) + __bfloat162float(l.b[3])) * s;
    dst[i4] = v;
}

// ============================================================================
extern "C" void kernel_launch(void* const* d_in, const int* in_sizes, int n_in,
                              void* d_out, int out_size)
{
    (void)in_sizes; (void)n_in; (void)out_size;
    const float* Q    = (const float*)d_in[0];
    const float* Km   = (const float*)d_in[1];
    const float* Wrel = (const float*)d_in[2];
    const float* Wq   = (const float*)d_in[3];
    const float* Wk   = (const float*)d_in[4];
    const float* Wqa  = (const float*)d_in[5];
    const float* Wka  = (const float*)d_in[6];
    float* out = (float*)d_out;

    __nv_bfloat16 *q2, *k2, *qw2, *w2t, *wp2t, *qph, *qpl, *kph, *kpl;
    float *aQ, *aK;
    cudaGetSymbolAddress((void**)&q2,   g_Q2);
    cudaGetSymbolAddress((void**)&k2,   g_K2);
    cudaGetSymbolAddress((void**)&qw2,  g_Qw2);
    cudaGetSymbolAddress((void**)&w2t,  g_W2t);
    cudaGetSymbolAddress((void**)&wp2t, g_Wp2t);
    cudaGetSymbolAddress((void**)&aQ,   g_accQ);
    cudaGetSymbolAddress((void**)&aK,   g_accK);
    cudaGetSymbolAddress((void**)&qph,  g_qph);
    cudaGetSymbolAddress((void**)&qpl,  g_qpl);
    cudaGetSymbolAddress((void**)&kph,  g_kph);
    cudaGetSymbolAddress((void**)&kpl,  g_kpl);

    cudaFuncSetAttribute(qw_slim_kernel,   cudaFuncAttributeMaxDynamicSharedMemorySize, SMEM_QWS);
    cudaFuncSetAttribute(proj_slim_kernel, cudaFuncAttributeMaxDynamicSharedMemorySize, SMEM_SLIM);
    cudaFuncSetAttribute(rel_fused_kernel, cudaFuncAttributeMaxDynamicSharedMemorySize, SMEM_FUSED);

    const dim3 blk(256);
    // ALL prep work in one launch (also makes rel_fused our 4th launch for ncu)
    prep_all_kernel<<<16768, blk>>>(Q, Km, Wrel, Wq, Wk, q2, k2, w2t, wp2t);
    // projections -> accumulator base values + bf16 hi/lo copies
    proj_slim_kernel<<<dim3(512, 2), blk, SMEM_SLIM>>>(
        q2, k2, wp2t, aQ, aK, qph, qpl, kph, kpl);
    // Qw (slim 64x128 tiles, 3 CTA/SM; n fastest for Q2 L2 reuse)
    qw_slim_kernel<<<dim3(2, 1024), blk, SMEM_QWS>>>(q2, w2t, qw2);
    // fused rel (chunk-set mainloop) + both score GEMMs -> REDs into accumulators
    rel_fused_kernel<<<dim3(4, 4, BN), blk, SMEM_FUSED>>>(qw2, k2, kph, kpl, qph, qpl, aQ, aK);
    // tanh-dot + softmax -> weights in d_out (fused)
    logits_kernel<<<dim3(BN, 2), 512>>>(aQ, aK, Wqa, Wka, out);
    // weighted outputs from compact bf16
    scale_kernel<<<dim3((BN * LN * DN) / 4 / 256, 2), 256>>>(q2, k2, out);
}